// round 13
// baseline (speedup 1.0000x reference)
#include <cuda_runtime.h>
#include <cuda_fp16.h>
#include <stdint.h>

#define FF 32
#define HH 160
#define BB 64
#define TT 256
#define TM 64
#define NTH 256
#define EAS 168      /* half stride for A images (>=160, ldmatrix-friendly) */
#define XSTR 33      /* x tile row stride (floats) */

typedef unsigned long long u64;

__device__ float g_weights[BB * FF];
/* B fragments: [t(35)][kt(10)][nt(20)][lane(32)] -> uint2 {b0,b1}
   tile slots: 0..31 = W2[f], 32 = oW1, 33 = oWg, 34 = oW2                    */
__device__ __align__(16) uint2 g_Bfrag[35 * 6400];
/* per-f parameter pack, 1280 floats per f:
   [0,320): W1/b1 interleaved pairs: pair i: {W1[2i],W1[2i+1],b1[2i],b1[2i+1]}
   [320,1280): 16 thread-groups x 60 floats:
       group g2 = nhq*4 + (l&3); within: b2@0, Wg@12, bg@24, lng@36, lnb@48,
       each 10 used floats (j*2+e), 2 pad.                                    */
__device__ __align__(16) float g_Par[FF * 1280];

/* ------------------------------ helpers ---------------------------------- */
__device__ __forceinline__ uint32_t smem_u32(const void* p) {
    uint32_t a;
    asm("{ .reg .u64 t; cvta.to.shared.u64 t, %1; cvt.u32.u64 %0, t; }" : "=r"(a) : "l"(p));
    return a;
}
__device__ __forceinline__ uint32_t pack_h2(float a, float b) {
    __half2 h = __floats2half2_rn(a, b);
    return *reinterpret_cast<uint32_t*>(&h);
}
__device__ __forceinline__ u64 packf2(float lo, float hi) {
    u64 r;
    asm("mov.b64 %0, {%1, %2};" : "=l"(r) : "f"(lo), "f"(hi));
    return r;
}
__device__ __forceinline__ void unpackf2(float& lo, float& hi, u64 v) {
    asm("mov.b64 {%0, %1}, %2;" : "=f"(lo), "=f"(hi) : "l"(v));
}
#define FMA2(d, a, b, c) asm("fma.rn.f32x2 %0, %1, %2, %3;" : "=l"(d) : "l"(a), "l"(b), "l"(c))
#define ADD2(d, a, b)    asm("add.rn.f32x2 %0, %1, %2;" : "=l"(d) : "l"(a), "l"(b))
#define MUL2(d, a, b)    asm("mul.rn.f32x2 %0, %1, %2;" : "=l"(d) : "l"(a), "l"(b))

__device__ __forceinline__ u64 fsig2(u64 z, u64 SC1, u64 SC2, u64 SC3, u64 SCH) {
    u64 z2, t;
    MUL2(z2, z, z);
    FMA2(t, z2, SC1, SC2);
    FMA2(t, z2, t, SC3);
    FMA2(t, z, t, SCH);
    return t;
}
__device__ __forceinline__ uint32_t agen2(u64 xg2, u64 w, u64 b,
                                          u64 C120, u64 C24, u64 C6, u64 SCH) {
    u64 z, z2, qq, p;
    FMA2(z, xg2, w, b);
    MUL2(z2, z, z);
    FMA2(qq, z, C120, C24);
    FMA2(qq, z, qq, C6);
    FMA2(qq, z, qq, SCH);
    FMA2(p, z2, qq, z);
    float zl, zh, pl, ph;
    unpackf2(zl, zh, z);
    unpackf2(pl, ph, p);
    float rl = zl > 0.f ? zl : pl;
    float rh = zh > 0.f ? zh : ph;
    return pack_h2(rl, rh);
}
__device__ __forceinline__ float fsigmoid(float z) {
    float z2 = z * z;
    float t = fmaf(z2, 2.0833333e-3f, -2.0833334e-2f);
    t = fmaf(z2, t, 0.25f);
    return fmaf(z, t, 0.5f);
}
__device__ __forceinline__ float felu(float z) {
    float p = fmaf(z, 8.3333333e-3f, 4.1666667e-2f);
    p = fmaf(z, p, 1.6666667e-1f);
    p = fmaf(z, p, 0.5f);
    p = fmaf(z, p, 1.0f);
    p = z * p;
    return z > 0.f ? z : p;
}
__device__ __forceinline__ void mma16816(float* c, uint32_t a0, uint32_t a1,
                                         uint32_t a2, uint32_t a3,
                                         uint32_t b0, uint32_t b1) {
    asm volatile(
        "mma.sync.aligned.m16n8k16.row.col.f32.f16.f16.f32 "
        "{%0,%1,%2,%3}, {%4,%5,%6,%7}, {%8,%9}, {%0,%1,%2,%3};"
        : "+f"(c[0]), "+f"(c[1]), "+f"(c[2]), "+f"(c[3])
        : "r"(a0), "r"(a1), "r"(a2), "r"(a3), "r"(b0), "r"(b1));
}
__device__ __forceinline__ void cp_async16(uint32_t saddr, const void* gptr) {
    asm volatile("cp.async.cg.shared.global [%0], [%1], 16;" :: "r"(saddr), "l"(gptr));
}
#define CP_COMMIT() asm volatile("cp.async.commit_group;" ::: "memory")
#define CP_WAIT0()  asm volatile("cp.async.wait_group 0;" ::: "memory")
#define CP_WAIT1()  asm volatile("cp.async.wait_group 1;" ::: "memory")
#define LDMX4(a0, a1, a2, a3, p)                                                 \
    asm volatile("ldmatrix.sync.aligned.m8n8.x4.shared.b16 {%0,%1,%2,%3}, [%4];" \
                 : "=r"(a0), "=r"(a1), "=r"(a2), "=r"(a3) : "r"(p))

/* gemm chunk: 5 k-tiles, 2 m-tiles per warp, B from smem stage */
__device__ __forceinline__ void gemm_chunk(float* acc, uint32_t ap0, uint32_t ap1,
                                           int h, const uint2* sb) {
#pragma unroll
    for (int kt = 0; kt < 5; ++kt) {
        uint32_t a0, a1, a2, a3, c0, c1, c2, c3;
        LDMX4(a0, a1, a2, a3, ap0 + (h * 5 + kt) * 32);
        LDMX4(c0, c1, c2, c3, ap1 + (h * 5 + kt) * 32);
#pragma unroll
        for (int j = 0; j < 5; ++j) {
            uint2 bv = sb[(kt * 20 + j) * 32];
            mma16816(acc + (j * 2 + 0) * 4, a0, a1, a2, a3, bv.x, bv.y);
            mma16816(acc + (j * 2 + 1) * 4, c0, c1, c2, c3, bv.x, bv.y);
        }
    }
}

/* --------------- kernel 0: merged prep (B fragments + params) + weights --- */
__global__ void pre_kernel(const float* __restrict__ W2,
                           const float* __restrict__ oW1,
                           const float* __restrict__ oW2,
                           const float* __restrict__ oWg,
                           const float* __restrict__ W1,
                           const float* __restrict__ b1,
                           const float* __restrict__ b2,
                           const float* __restrict__ Wg,
                           const float* __restrict__ bg,
                           const float* __restrict__ lng,
                           const float* __restrict__ lnb,
                           const float* __restrict__ x,
                           const float* __restrict__ Ww,
                           const float* __restrict__ bw,
                           float* __restrict__ out_tail) {
    if (blockIdx.x >= BB) {
        int u = blockIdx.x - BB;
        int t = u >> 2, part = u & 3;
        const float* src = (t < 32) ? (W2 + (size_t)t * HH * HH)
                                    : (t == 32 ? oW1 : (t == 33 ? oWg : oW2));
        int base = part * 1600;
        for (int k = threadIdx.x; k < 1600; k += blockDim.x) {
            int idx = base + k;
            int kt = idx / 640;
            int nt = (idx / 32) % 20;
            int l  = idx & 31;
            int k0 = kt * 16 + (l & 3) * 2;
            int n  = nt * 8 + (l >> 2);
            uint2 v;
            v.x = pack_h2(src[k0 * HH + n],       src[(k0 + 1) * HH + n]);
            v.y = pack_h2(src[(k0 + 8) * HH + n], src[(k0 + 9) * HH + n]);
            g_Bfrag[(size_t)t * 6400 + idx] = v;
        }
        if (t < FF && part == 0) {
            const float* srcs[7] = { W1 + t * HH, b1 + t * HH, b2 + t * HH,
                                     Wg + t * HH, bg + t * HH,
                                     lng + t * HH, lnb + t * HH };
            /* zero pad slots (only the 2-float pads per 12-float group) */
            for (int jl = threadIdx.x; jl < 1120; jl += blockDim.x) {
                int a = jl / 160, c = jl - a * 160;
                int p;
                if (a == 0) {                 /* W1 */
                    p = (c >> 1) * 4 + (c & 1);
                } else if (a == 1) {          /* b1 */
                    p = (c >> 1) * 4 + 2 + (c & 1);
                } else {                      /* fragment blocks */
                    int g = c / 40, rem = c - g * 40;
                    int j = rem >> 3, tt = (rem >> 1) & 3, e = rem & 1;
                    int g2 = g * 4 + tt;
                    p = 320 + g2 * 60 + (a - 2) * 12 + j * 2 + e;
                }
                g_Par[t * 1280 + p] = srcs[a][c];
            }
        }
        return;
    }
    int b = blockIdx.x;
    int tid = threadIdx.x;
    int c = tid & 31, g = tid >> 5;
    const float* xb = x + b * (TT * FF);
    float acc = 0.f;
#pragma unroll 4
    for (int r = g; r < TT * FF; r += 8) acc = fmaf(xb[r], Ww[r * FF + c], acc);
    __shared__ float red[8][32];
    red[g][c] = acc;
    __syncthreads();
    if (tid < 32) {
        float s = 0.f;
#pragma unroll
        for (int i = 0; i < 8; ++i) s += red[i][tid];
        s += bw[tid];
        float m = s;
#pragma unroll
        for (int o = 16; o; o >>= 1) m = fmaxf(m, __shfl_xor_sync(0xffffffffu, m, o));
        float e = expf(s - m);
        float se = e;
#pragma unroll
        for (int o = 16; o; o >>= 1) se += __shfl_xor_sync(0xffffffffu, se, o);
        float w = e / se;
        g_weights[b * 32 + tid] = w;
        out_tail[b * 32 + tid] = w;
    }
}

/* ------------------------- kernel 1: fused VSN (HMMA) ---------------------
   SMEM (bytes):
     xs      [0,       8448)   64 x 33 fp32
     eaA     [8448,   29952)   64 x 168 fp16
     red     [29952,  32000)   64 x 8 fp32
     pbuf    [32000,  47360)   3 x 5120 param ring
     Bstage  [47360,  98560)   2 x 25600 cp.async double buffer              */
#define OFF_EAA  8448
#define OFF_RED  29952
#define OFF_PBUF 32000
#define OFF_BST  47360
#define CHKB     25600
#define SMEM_TOTAL 98560

__global__ void __launch_bounds__(NTH, 2)
fused_mma(const float* __restrict__ x,
          const float* __restrict__ ob1, const float* __restrict__ ob2,
          const float* __restrict__ obg,
          const float* __restrict__ olng, const float* __restrict__ olnb,
          float* __restrict__ out) {
    extern __shared__ char smem[];
    float*  xs  = (float*)smem;
    __half* eaA = (__half*)(smem + OFF_EAA);
    float*  red = (float*)(smem + OFF_RED);
    const uint32_t sbase = smem_u32(smem);

    const int tid = threadIdx.x;
    const int l = tid & 31, wid = tid >> 5;
    const int mg = wid >> 2, nhq = wid & 3;
    const int rA = mg * 32 + (l >> 2);
    int rr[4];
    rr[0] = rA; rr[1] = rA + 8; rr[2] = rA + 16; rr[3] = rA + 24;
    const int colbq = nhq * 40;
    const int colt = (l & 3) * 2;
    const int pblk = 320 + (nhq * 4 + (l & 3)) * 60;   /* epilogue block base */
    const int m0 = blockIdx.x * TM;
    const int bb = blockIdx.x >> 2;

    const int lrow = mg * 32 + (l & 15);
    const int lcol = (l >> 4) * 8;
    const uint32_t aAp0 = sbase + OFF_EAA + (lrow * EAS + lcol) * 2;
    const uint32_t aAp1 = aAp0 + 16 * EAS * 2;
    const int sboff = nhq * 160 + l;

    const int grow = tid >> 2;
    const int gpair = (tid & 3) * 20;    /* W1b1 pair base */

    const u64 SC1  = packf2(2.0833333e-3f, 2.0833333e-3f);
    const u64 SC2  = packf2(-2.0833334e-2f, -2.0833334e-2f);
    const u64 SC3  = packf2(0.25f, 0.25f);
    const u64 SCH  = packf2(0.5f, 0.5f);
    const u64 C120 = packf2(8.3333333e-3f, 8.3333333e-3f);
    const u64 C24  = packf2(4.1666667e-2f, 4.1666667e-2f);
    const u64 C6   = packf2(1.6666667e-1f, 1.6666667e-1f);

    const uint2* buf0 = (const uint2*)(smem + OFF_BST) + sboff;
    const uint2* buf1 = (const uint2*)(smem + OFF_BST + CHKB) + sboff;

#define HBAR() asm volatile("bar.sync %0, 128;" :: "r"(1 + mg) : "memory")

#define PREF_CHUNK(cc, bufi) do {                                                \
    const uint4* gsrc = (const uint4*)g_Bfrag + (size_t)(cc) * 1600;             \
    const uint32_t dst = sbase + OFF_BST + (bufi) * CHKB;                        \
    for (int j = tid; j < 1600; j += NTH)                                        \
        cp_async16(dst + j * 16, gsrc + j);                                      \
} while (0)

#define PREF_PAR(ff) do {                                                        \
    const float4* psrc = (const float4*)g_Par + (size_t)(ff) * 320;              \
    const uint32_t pdst = sbase + OFF_PBUF + ((ff) % 3) * 5120;                  \
    for (int j = tid; j < 320; j += NTH)                                         \
        cp_async16(pdst + j * 16, psrc + j);                                     \
} while (0)

#define AGEN(ff, slot) do {                                                      \
    const float* pbn = (const float*)(smem + OFF_PBUF) + (slot) * 1280;          \
    const float xvg = xs[grow * XSTR + (ff)];                                    \
    const u64 xg2 = packf2(xvg, xvg);                                            \
    const ulonglong2* Wb = (const ulonglong2*)pbn + gpair;                       \
    uint4* eg = (uint4*)(eaA + grow * EAS + (tid & 3) * 40);                     \
    _Pragma("unroll")                                                            \
    for (int q = 0; q < 5; ++q) {                                                \
        ulonglong2 e0 = Wb[q * 4 + 0];                                           \
        ulonglong2 e1 = Wb[q * 4 + 1];                                           \
        ulonglong2 e2 = Wb[q * 4 + 2];                                           \
        ulonglong2 e3 = Wb[q * 4 + 3];                                           \
        uint4 o;                                                                 \
        o.x = agen2(xg2, e0.x, e0.y, C120, C24, C6, SCH);                        \
        o.y = agen2(xg2, e1.x, e1.y, C120, C24, C6, SCH);                        \
        o.z = agen2(xg2, e2.x, e2.y, C120, C24, C6, SCH);                        \
        o.w = agen2(xg2, e3.x, e3.y, C120, C24, C6, SCH);                        \
        eg[q] = o;                                                               \
    }                                                                            \
} while (0)

/* epilogue for feature fe; acc is reused in place to hold feat values */
#define EPILOGUE(fe, slotE) do {                                                 \
    const float* pe = (const float*)(smem + OFF_PBUF) + (slotE) * 1280 + pblk;   \
    float wbf = g_weights[bb * FF + (fe)];                                       \
    u64 xv2[4], nxv2[4], nc02[4], s1p[4], s2p[4];                                \
    float c0v[4];                                                                \
    _Pragma("unroll")                                                            \
    for (int ri = 0; ri < 4; ++ri) {                                             \
        float xv = xs[rr[ri] * XSTR + (fe)];                                     \
        float c0 = 0.5f * xv;                                                    \
        xv2[ri]  = packf2(xv, xv);                                               \
        nxv2[ri] = packf2(-xv, -xv);                                             \
        nc02[ri] = packf2(-c0, -c0);                                             \
        c0v[ri]  = c0;                                                           \
        s1p[ri] = 0ull; s2p[ri] = 0ull;                                          \
    }                                                                            \
    {                                                                            \
        ulonglong2 b01 = *(const ulonglong2*)(pe + 0);                           \
        ulonglong2 b23 = *(const ulonglong2*)(pe + 4);                           \
        u64        b4  = *(const u64*)(pe + 8);                                  \
        ulonglong2 w01 = *(const ulonglong2*)(pe + 12);                          \
        ulonglong2 w23 = *(const ulonglong2*)(pe + 16);                          \
        u64        w4  = *(const u64*)(pe + 20);                                 \
        ulonglong2 g01 = *(const ulonglong2*)(pe + 24);                          \
        ulonglong2 g23 = *(const ulonglong2*)(pe + 28);                          \
        u64        g4  = *(const u64*)(pe + 32);                                 \
        u64 b2a[5] = { b01.x, b01.y, b23.x, b23.y, b4 };                         \
        u64 wga[5] = { w01.x, w01.y, w23.x, w23.y, w4 };                         \
        u64 bga[5] = { g01.x, g01.y, g23.x, g23.y, g4 };                         \
        _Pragma("unroll")                                                        \
        for (int jv = 0; jv < 5; ++jv) {                                         \
            _Pragma("unroll")                                                    \
            for (int ri = 0; ri < 4; ++ri) {                                     \
                int idx = (jv * 2 + (ri >> 1)) * 4 + (ri & 1) * 2;               \
                u64 ap = packf2(acc[idx], acc[idx + 1]);                         \
                u64 a2; ADD2(a2, ap, b2a[jv]);                                   \
                u64 gz; FMA2(gz, xv2[ri], wga[jv], bga[jv]);                     \
                u64 gv = fsig2(gz, SC1, SC2, SC3, SCH);                          \
                u64 dmx; ADD2(dmx, a2, nxv2[ri]);                                \
                u64 ft; FMA2(ft, gv, dmx, xv2[ri]);                              \
                unpackf2(acc[idx], acc[idx + 1], ft);   /* feat -> acc */        \
                u64 d; ADD2(d, ft, nc02[ri]);                                    \
                ADD2(s1p[ri], s1p[ri], d);                                       \
                FMA2(s2p[ri], d, d, s2p[ri]);                                    \
            }                                                                    \
        }                                                                        \
    }                                                                            \
    float s1v[4], s2v[4];                                                        \
    _Pragma("unroll")                                                            \
    for (int ri = 0; ri < 4; ++ri) {                                             \
        float a_, b_;                                                            \
        unpackf2(a_, b_, s1p[ri]); s1v[ri] = a_ + b_;                            \
        unpackf2(a_, b_, s2p[ri]); s2v[ri] = a_ + b_;                            \
    }                                                                            \
    _Pragma("unroll")                                                            \
    for (int ri = 0; ri < 4; ++ri) {                                             \
        _Pragma("unroll")                                                        \
        for (int o = 1; o < 4; o <<= 1) {                                        \
            s1v[ri] += __shfl_xor_sync(0xffffffffu, s1v[ri], o);                 \
            s2v[ri] += __shfl_xor_sync(0xffffffffu, s2v[ri], o);                 \
        }                                                                        \
    }                                                                            \
    if ((l & 3) == 0) {                                                          \
        _Pragma("unroll")                                                        \
        for (int ri = 0; ri < 4; ++ri)                                           \
            *(float2*)(red + rr[ri] * 8 + nhq * 2) = make_float2(s1v[ri], s2v[ri]); \
    }                                                                            \
    HBAR();                                                                      \
    u64 inv2[4], nmi2[4];                                                        \
    _Pragma("unroll")                                                            \
    for (int ri = 0; ri < 4; ++ri) {                                             \
        float4 qa = *(const float4*)(red + rr[ri] * 8);                          \
        float4 qb = *(const float4*)(red + rr[ri] * 8 + 4);                      \
        float S1 = (qa.x + qa.z) + (qb.x + qb.z);                                \
        float S2 = (qa.y + qa.w) + (qb.y + qb.w);                                \
        float dm = S1 * (1.f / 160.f);                                           \
        float var = fmaf(-dm, dm, S2 * (1.f / 160.f));                           \
        float inv = rsqrtf(var + 1e-3f);                                         \
        float nmi = -(c0v[ri] + dm) * inv;                                       \
        inv2[ri] = packf2(inv, inv);                                             \
        nmi2[ri] = packf2(nmi, nmi);                                             \
    }                                                                            \
    {                                                                            \
        u64 wbf2 = packf2(wbf, wbf);                                             \
        ulonglong2 l01 = *(const ulonglong2*)(pe + 36);                          \
        ulonglong2 l23 = *(const ulonglong2*)(pe + 40);                          \
        u64        l4  = *(const u64*)(pe + 44);                                 \
        ulonglong2 m01 = *(const ulonglong2*)(pe + 48);                          \
        ulonglong2 m23 = *(const ulonglong2*)(pe + 52);                          \
        u64        m4  = *(const u64*)(pe + 56);                                 \
        u64 lga[5] = { l01.x, l01.y, l23.x, l23.y, l4 };                         \
        u64 lba[5] = { m01.x, m01.y, m23.x, m23.y, m4 };                         \
        _Pragma("unroll")                                                        \
        for (int jv = 0; jv < 5; ++jv) {                                         \
            _Pragma("unroll")                                                    \
            for (int ri = 0; ri < 4; ++ri) {                                     \
                int idx = (jv * 2 + (ri >> 1)) * 4 + (ri & 1) * 2;               \
                u64 ftp = packf2(acc[idx], acc[idx + 1]);                        \
                u64 yt; FMA2(yt, ftp, inv2[ri], nmi2[ri]);                       \
                u64 y;  FMA2(y, yt, lga[jv], lba[jv]);                           \
                FMA2(comb2[jv * 4 + ri], wbf2, y, comb2[jv * 4 + ri]);           \
            }                                                                    \
        }                                                                        \
    }                                                                            \
} while (0)

    /* ------------------------------ preamble ------------------------------ */
    {
        const float4* xsrc = (const float4*)(x + (size_t)m0 * FF);
        for (int i = tid; i < TM * FF / 4; i += NTH) {
            float4 v = xsrc[i];
            float* d = xs + (i >> 3) * XSTR + ((i & 7) << 2);
            d[0] = v.x; d[1] = v.y; d[2] = v.z; d[3] = v.w;
        }
    }
    PREF_PAR(0);
    CP_COMMIT();
    u64 comb2[20];
#pragma unroll
    for (int i = 0; i < 20; ++i) comb2[i] = 0ull;
    CP_WAIT0();
    __syncthreads();

    float acc[40];

    /* ========================= phase 1: f loop ============================ */
    for (int f = 0; f < FF; ++f) {
        const int sc = f % 3;
        __syncthreads();
        PREF_CHUNK(2 * f, 0);
        if (f + 1 < FF) PREF_PAR(f + 1);
        CP_COMMIT();
        PREF_CHUNK(2 * f + 1, 1);
        CP_COMMIT();

        AGEN(f, sc);
        if (f > 0) EPILOGUE(f - 1, (f - 1) % 3);

#pragma unroll
        for (int i = 0; i < 40; ++i) acc[i] = 0.f;
        CP_WAIT1();
        __syncthreads();
        gemm_chunk(acc, aAp0, aAp1, 0, buf0);
        CP_WAIT0();
        __syncthreads();
        gemm_chunk(acc, aAp0, aAp1, 1, buf1);
    }

    /* ========================= phase 2: output MLP ======================== */
    __syncthreads();
    PREF_CHUNK(64, 0); CP_COMMIT();
    PREF_CHUNK(65, 1); CP_COMMIT();
    EPILOGUE(31, 31 % 3);
#pragma unroll
    for (int jv = 0; jv < 5; ++jv)
#pragma unroll
        for (int ri = 0; ri < 4; ++ri) {
            float cx, cy;
            unpackf2(cx, cy, comb2[jv * 4 + ri]);
            *(uint32_t*)(eaA + rr[ri] * EAS + colbq + jv * 8 + colt) = pack_h2(cx, cy);
        }

    /* G1: h1 = elu(comb @ oW1 + ob1) */
#pragma unroll
    for (int i = 0; i < 40; ++i) acc[i] = 0.f;
    CP_WAIT1(); __syncthreads(); gemm_chunk(acc, aAp0, aAp1, 0, buf0);
    CP_WAIT0(); __syncthreads(); gemm_chunk(acc, aAp0, aAp1, 1, buf1);
    uint32_t h1p[20];
#pragma unroll
    for (int jv = 0; jv < 5; ++jv)
#pragma unroll
        for (int ri = 0; ri < 4; ++ri) {
            int idx = (jv * 2 + (ri >> 1)) * 4 + (ri & 1) * 2;
            int col = colbq + jv * 8 + colt;
            float2 vb = *(const float2*)(ob1 + col);
            h1p[jv * 4 + ri] =
                pack_h2(felu(acc[idx] + vb.x), felu(acc[idx + 1] + vb.y));
        }

    /* G3: og = sigmoid(comb @ oWg + obg) */
    __syncthreads();
    PREF_CHUNK(66, 0); CP_COMMIT();
    PREF_CHUNK(67, 1); CP_COMMIT();
#pragma unroll
    for (int i = 0; i < 40; ++i) acc[i] = 0.f;
    CP_WAIT1(); __syncthreads(); gemm_chunk(acc, aAp0, aAp1, 0, buf0);
    CP_WAIT0(); __syncthreads(); gemm_chunk(acc, aAp0, aAp1, 1, buf1);
    u64 og2[20];
#pragma unroll
    for (int jv = 0; jv < 5; ++jv)
#pragma unroll
        for (int ri = 0; ri < 4; ++ri) {
            int idx = (jv * 2 + (ri >> 1)) * 4 + (ri & 1) * 2;
            int col = colbq + jv * 8 + colt;
            float2 vb = *(const float2*)(obg + col);
            og2[jv * 4 + ri] = packf2(fsigmoid(acc[idx] + vb.x),
                                      fsigmoid(acc[idx + 1] + vb.y));
        }

    /* G2: oa = h1 @ oW2 + ob2 */
    __syncthreads();
    PREF_CHUNK(68, 0); CP_COMMIT();
    PREF_CHUNK(69, 1); CP_COMMIT();
#pragma unroll
    for (int jv = 0; jv < 5; ++jv)
#pragma unroll
        for (int ri = 0; ri < 4; ++ri)
            *(uint32_t*)(eaA + rr[ri] * EAS + colbq + jv * 8 + colt) = h1p[jv * 4 + ri];
#pragma unroll
    for (int i = 0; i < 40; ++i) acc[i] = 0.f;
    CP_WAIT1(); __syncthreads(); gemm_chunk(acc, aAp0, aAp1, 0, buf0);
    CP_WAIT0(); __syncthreads(); gemm_chunk(acc, aAp0, aAp1, 1, buf1);

    /* combine + final LN + fragment-layout store */
    {
        u64 vp[20];
        float s1v[4] = {0.f, 0.f, 0.f, 0.f};
        float s2v[4] = {0.f, 0.f, 0.f, 0.f};
#pragma unroll
        for (int jv = 0; jv < 5; ++jv)
#pragma unroll
            for (int ri = 0; ri < 4; ++ri) {
                int idx = (jv * 2 + (ri >> 1)) * 4 + (ri & 1) * 2;
                int col = colbq + jv * 8 + colt;
                float2 vb = *(const float2*)(ob2 + col);
                float oax = acc[idx] + vb.x;
                float oay = acc[idx + 1] + vb.y;
                float ogx, ogy, cx, cy;
                unpackf2(ogx, ogy, og2[jv * 4 + ri]);
                unpackf2(cx, cy, comb2[jv * 4 + ri]);
                float vx = fmaf(ogx, oax - cx, cx);
                float vy = fmaf(ogy, oay - cy, cy);
                vp[jv * 4 + ri] = packf2(vx, vy);
                s1v[ri] += vx + vy;
                s2v[ri] = fmaf(vx, vx, s2v[ri]);
                s2v[ri] = fmaf(vy, vy, s2v[ri]);
            }
#pragma unroll
        for (int ri = 0; ri < 4; ++ri) {
#pragma unroll
            for (int o = 1; o < 4; o <<= 1) {
                s1v[ri] += __shfl_xor_sync(0xffffffffu, s1v[ri], o);
                s2v[ri] += __shfl_xor_sync(0xffffffffu, s2v[ri], o);
            }
        }
        if ((l & 3) == 0) {
#pragma unroll
            for (int ri = 0; ri < 4; ++ri)
                *(float2*)(red + rr[ri] * 8 + nhq * 2) = make_float2(s1v[ri], s2v[ri]);
        }
        HBAR();
        float meanv[4], invv[4];
#pragma unroll
        for (int ri = 0; ri < 4; ++ri) {
            float4 qa = *(const float4*)(red + rr[ri] * 8);
            float4 qb = *(const float4*)(red + rr[ri] * 8 + 4);
            float S1 = (qa.x + qa.z) + (qb.x + qb.z);
            float S2 = (qa.y + qa.w) + (qb.y + qb.w);
            float mean = S1 * (1.f / 160.f);
            float var = fmaf(-mean, mean, S2 * (1.f / 160.f));
            meanv[ri] = mean;
            invv[ri] = rsqrtf(var + 1e-3f);
        }
#pragma unroll
        for (int jv = 0; jv < 5; ++jv)
#pragma unroll
            for (int ri = 0; ri < 4; ++ri) {
                int col = colbq + jv * 8 + colt;
                float2 lg = *(const float2*)(olng + col);
                float2 lb = *(const float2*)(olnb + col);
                float vx, vy;
                unpackf2(vx, vy, vp[jv * 4 + ri]);
                float2 o;
                o.x = fmaf((vx - meanv[ri]) * invv[ri], lg.x, lb.x);
                o.y = fmaf((vy - meanv[ri]) * invv[ri], lg.y, lb.y);
                *(float2*)(out + (size_t)(m0 + rr[ri]) * HH + col) = o;
            }
    }
#undef HBAR
#undef AGEN
#undef EPILOGUE
#undef PREF_CHUNK
#undef PREF_PAR
}

/* --------------------------------- launch --------------------------------- */
extern "C" void kernel_launch(void* const* d_in, const int* in_sizes, int n_in,
                              void* d_out, int out_size) {
    const float* x    = (const float*)d_in[0];
    const float* W1   = (const float*)d_in[1];
    const float* b1   = (const float*)d_in[2];
    const float* W2   = (const float*)d_in[3];
    const float* b2   = (const float*)d_in[4];
    const float* Wg   = (const float*)d_in[5];
    const float* bg   = (const float*)d_in[6];
    const float* lng  = (const float*)d_in[7];
    const float* lnb  = (const float*)d_in[8];
    const float* Ww   = (const float*)d_in[9];
    const float* bw   = (const float*)d_in[10];
    const float* oW1  = (const float*)d_in[11];
    const float* ob1  = (const float*)d_in[12];
    const float* oW2  = (const float*)d_in[13];
    const float* ob2  = (const float*)d_in[14];
    const float* oWg  = (const float*)d_in[15];
    const float* obg  = (const float*)d_in[16];
    const float* olng = (const float*)d_in[17];
    const float* olnb = (const float*)d_in[18];
    float* out = (float*)d_out;

    cudaFuncSetAttribute(fused_mma, cudaFuncAttributeMaxDynamicSharedMemorySize,
                         SMEM_TOTAL);

    pre_kernel<<<BB + 140, 256>>>(W2, oW1, oW2, oWg,
                                  W1, b1, b2, Wg, bg, lng, lnb,
                                  x, Ww, bw, out + (size_t)BB * TT * HH);
    fused_mma<<<(BB * TT) / TM, NTH, SMEM_TOTAL>>>(
        x, ob1, ob2, obg, olng, olnb, out);
}

// round 14
// speedup vs baseline: 1.1992x; 1.1992x over previous
#include <cuda_runtime.h>
#include <cuda_fp16.h>
#include <stdint.h>

#define FF 32
#define HH 160
#define BB 64
#define TT 256
#define TM 64
#define NTH 256
#define EAS 168      /* half stride for A images (>=160, ldmatrix-friendly) */
#define XSTR 33      /* x tile row stride (floats) */

typedef unsigned long long u64;

__device__ float g_weights[BB * FF];
/* B fragments: [t(35)][kt(10)][nt(20)][lane(32)] -> uint2 {b0,b1}
   tile slots: 0..31 = W2[f], 32 = oW1, 33 = oWg, 34 = oW2                    */
__device__ __align__(16) uint2 g_Bfrag[35 * 6400];
/* per-f parameter pack, 1280 floats per f:
   [0,160)=W1  [160,320)=b1  then 5 fragment-major arrays of 192 floats:
   b2@320, Wg@512, bg@704, lng@896, lnb@1088. */
__device__ __align__(16) float g_Par[FF * 1280];

/* ------------------------------ helpers ---------------------------------- */
__device__ __forceinline__ uint32_t smem_u32(const void* p) {
    uint32_t a;
    asm("{ .reg .u64 t; cvta.to.shared.u64 t, %1; cvt.u32.u64 %0, t; }" : "=r"(a) : "l"(p));
    return a;
}
__device__ __forceinline__ uint32_t pack_h2(float a, float b) {
    __half2 h = __floats2half2_rn(a, b);
    return *reinterpret_cast<uint32_t*>(&h);
}
__device__ __forceinline__ u64 packf2(float lo, float hi) {
    u64 r;
    asm("mov.b64 %0, {%1, %2};" : "=l"(r) : "f"(lo), "f"(hi));
    return r;
}
__device__ __forceinline__ void unpackf2(float& lo, float& hi, u64 v) {
    asm("mov.b64 {%0, %1}, %2;" : "=f"(lo), "=f"(hi) : "l"(v));
}
#define FMA2(d, a, b, c) asm("fma.rn.f32x2 %0, %1, %2, %3;" : "=l"(d) : "l"(a), "l"(b), "l"(c))
#define ADD2(d, a, b)    asm("add.rn.f32x2 %0, %1, %2;" : "=l"(d) : "l"(a), "l"(b))
#define MUL2(d, a, b)    asm("mul.rn.f32x2 %0, %1, %2;" : "=l"(d) : "l"(a), "l"(b))

__device__ __forceinline__ u64 fsig2(u64 z, u64 SC1, u64 SC2, u64 SC3, u64 SCH) {
    u64 z2, t;
    MUL2(z2, z, z);
    FMA2(t, z2, SC1, SC2);
    FMA2(t, z2, t, SC3);
    FMA2(t, z, t, SCH);
    return t;
}
__device__ __forceinline__ uint32_t agen2(u64 xg2, u64 w, u64 b,
                                          u64 C120, u64 C24, u64 C6, u64 SCH) {
    u64 z, z2, qq, p;
    FMA2(z, xg2, w, b);
    MUL2(z2, z, z);
    FMA2(qq, z, C120, C24);
    FMA2(qq, z, qq, C6);
    FMA2(qq, z, qq, SCH);
    FMA2(p, z2, qq, z);
    float zl, zh, pl, ph;
    unpackf2(zl, zh, z);
    unpackf2(pl, ph, p);
    float rl = zl > 0.f ? zl : pl;
    float rh = zh > 0.f ? zh : ph;
    return pack_h2(rl, rh);
}
__device__ __forceinline__ float fsigmoid(float z) {
    float z2 = z * z;
    float t = fmaf(z2, 2.0833333e-3f, -2.0833334e-2f);
    t = fmaf(z2, t, 0.25f);
    return fmaf(z, t, 0.5f);
}
__device__ __forceinline__ float felu(float z) {
    float p = fmaf(z, 8.3333333e-3f, 4.1666667e-2f);
    p = fmaf(z, p, 1.6666667e-1f);
    p = fmaf(z, p, 0.5f);
    p = fmaf(z, p, 1.0f);
    p = z * p;
    return z > 0.f ? z : p;
}
__device__ __forceinline__ void mma16816(float* c, uint32_t a0, uint32_t a1,
                                         uint32_t a2, uint32_t a3,
                                         uint32_t b0, uint32_t b1) {
    asm volatile(
        "mma.sync.aligned.m16n8k16.row.col.f32.f16.f16.f32 "
        "{%0,%1,%2,%3}, {%4,%5,%6,%7}, {%8,%9}, {%0,%1,%2,%3};"
        : "+f"(c[0]), "+f"(c[1]), "+f"(c[2]), "+f"(c[3])
        : "r"(a0), "r"(a1), "r"(a2), "r"(a3), "r"(b0), "r"(b1));
}
__device__ __forceinline__ void cp_async16(uint32_t saddr, const void* gptr) {
    asm volatile("cp.async.cg.shared.global [%0], [%1], 16;" :: "r"(saddr), "l"(gptr));
}
#define CP_COMMIT() asm volatile("cp.async.commit_group;" ::: "memory")
#define CP_WAIT0()  asm volatile("cp.async.wait_group 0;" ::: "memory")
#define CP_WAIT1()  asm volatile("cp.async.wait_group 1;" ::: "memory")
#define LDMX4(a0, a1, a2, a3, p)                                                 \
    asm volatile("ldmatrix.sync.aligned.m8n8.x4.shared.b16 {%0,%1,%2,%3}, [%4];" \
                 : "=r"(a0), "=r"(a1), "=r"(a2), "=r"(a3) : "r"(p))

/* gemm chunk: 5 k-tiles, 2 m-tiles per warp, B from smem stage */
__device__ __forceinline__ void gemm_chunk(float* acc, uint32_t ap0, uint32_t ap1,
                                           int h, const uint2* sb) {
#pragma unroll
    for (int kt = 0; kt < 5; ++kt) {
        uint32_t a0, a1, a2, a3, c0, c1, c2, c3;
        LDMX4(a0, a1, a2, a3, ap0 + (h * 5 + kt) * 32);
        LDMX4(c0, c1, c2, c3, ap1 + (h * 5 + kt) * 32);
#pragma unroll
        for (int j = 0; j < 5; ++j) {
            uint2 bv = sb[(kt * 20 + j) * 32];
            mma16816(acc + (j * 2 + 0) * 4, a0, a1, a2, a3, bv.x, bv.y);
            mma16816(acc + (j * 2 + 1) * 4, c0, c1, c2, c3, bv.x, bv.y);
        }
    }
}

/* --------------- kernel 0: merged prep (B fragments + params) + weights ---
   blocks [0,64): selection weights (4-accumulator deep-MLP version)
   blocks [64,99): per-tile fragment conversion via smem staging             */
__global__ void pre_kernel(const float* __restrict__ W2,
                           const float* __restrict__ oW1,
                           const float* __restrict__ oW2,
                           const float* __restrict__ oWg,
                           const float* __restrict__ W1,
                           const float* __restrict__ b1,
                           const float* __restrict__ b2,
                           const float* __restrict__ Wg,
                           const float* __restrict__ bg,
                           const float* __restrict__ lng,
                           const float* __restrict__ lnb,
                           const float* __restrict__ x,
                           const float* __restrict__ Ww,
                           const float* __restrict__ bw,
                           float* __restrict__ out_tail) {
    extern __shared__ float stile[];   /* 160x160 fp32 = 102400 B (conv blocks) */
    if (blockIdx.x >= BB) {
        int t = blockIdx.x - BB;   /* 0..34 */
        const float* src = (t < 32) ? (W2 + (size_t)t * HH * HH)
                                    : (t == 32 ? oW1 : (t == 33 ? oWg : oW2));
        /* stage tile coalesced */
        {
            const float4* s4 = (const float4*)src;
            float4* d4 = (float4*)stile;
            for (int i = threadIdx.x; i < HH * HH / 4; i += blockDim.x)
                d4[i] = s4[i];
        }
        __syncthreads();
        /* fragment conversion: scattered smem reads, coalesced gmem writes */
        for (int idx = threadIdx.x; idx < 6400; idx += blockDim.x) {
            int kt = idx / 640;
            int nt = (idx / 32) % 20;
            int l  = idx & 31;
            int k0 = kt * 16 + (l & 3) * 2;
            int n  = nt * 8 + (l >> 2);
            uint2 v;
            v.x = pack_h2(stile[k0 * HH + n],       stile[(k0 + 1) * HH + n]);
            v.y = pack_h2(stile[(k0 + 8) * HH + n], stile[(k0 + 9) * HH + n]);
            g_Bfrag[(size_t)t * 6400 + idx] = v;
        }
        /* per-f parameter pack (round-12 fragment-major layout) */
        if (t < FF) {
            const float* srcs[7] = { W1 + t * HH, b1 + t * HH, b2 + t * HH,
                                     Wg + t * HH, bg + t * HH,
                                     lng + t * HH, lnb + t * HH };
            for (int jl = threadIdx.x; jl < 1120; jl += blockDim.x) {
                int a = jl / 160, c = jl - a * 160;
                int p;
                if (a < 2) {
                    p = a * 160 + c;
                } else {
                    int g = c / 40, rem = c - g * 40;
                    int j = rem >> 3, tt = (rem >> 1) & 3, e = rem & 1;
                    p = 320 + (a - 2) * 192 + g * 48 + tt * 12 + j * 2 + e;
                }
                g_Par[t * 1280 + p] = srcs[a][c];
            }
        }
        return;
    }
    /* selection weights: deep-MLP dot products */
    int b = blockIdx.x;
    int tid = threadIdx.x;
    int c = tid & 31, g = tid >> 5;
    const float* xb = x + b * (TT * FF);
    float a0 = 0.f, a1 = 0.f, a2 = 0.f, a3 = 0.f;
#pragma unroll 4
    for (int i = 0; i < TT * FF; i += 32) {
        int r = g + i;
        a0 = fmaf(xb[r],      Ww[r * FF + c],        a0);
        a1 = fmaf(xb[r + 8],  Ww[(r + 8) * FF + c],  a1);
        a2 = fmaf(xb[r + 16], Ww[(r + 16) * FF + c], a2);
        a3 = fmaf(xb[r + 24], Ww[(r + 24) * FF + c], a3);
    }
    float acc = (a0 + a1) + (a2 + a3);
    __shared__ float red[8][32];
    red[g][c] = acc;
    __syncthreads();
    if (tid < 32) {
        float s = 0.f;
#pragma unroll
        for (int i = 0; i < 8; ++i) s += red[i][tid];
        s += bw[tid];
        float m = s;
#pragma unroll
        for (int o = 16; o; o >>= 1) m = fmaxf(m, __shfl_xor_sync(0xffffffffu, m, o));
        float e = expf(s - m);
        float se = e;
#pragma unroll
        for (int o = 16; o; o >>= 1) se += __shfl_xor_sync(0xffffffffu, se, o);
        float w = e / se;
        g_weights[b * 32 + tid] = w;
        out_tail[b * 32 + tid] = w;
    }
}

/* ------------------------- kernel 1: fused VSN (HMMA) ---------------------
   (identical to the round-12 kernel)
   SMEM (bytes):
     xs      [0,       8448)   64 x 33 fp32
     eaA     [8448,   29952)   64 x 168 fp16
     red     [29952,  32000)   64 x 8 fp32
     pbuf    [32000,  47360)   3 x 5120 param ring
     Bstage  [47360,  98560)   2 x 25600 cp.async double buffer              */
#define OFF_EAA  8448
#define OFF_RED  29952
#define OFF_PBUF 32000
#define OFF_BST  47360
#define CHKB     25600
#define SMEM_TOTAL 98560

__global__ void __launch_bounds__(NTH, 2)
fused_mma(const float* __restrict__ x,
          const float* __restrict__ ob1, const float* __restrict__ ob2,
          const float* __restrict__ obg,
          const float* __restrict__ olng, const float* __restrict__ olnb,
          float* __restrict__ out) {
    extern __shared__ char smem[];
    float*  xs  = (float*)smem;
    __half* eaA = (__half*)(smem + OFF_EAA);
    float*  red = (float*)(smem + OFF_RED);
    const uint32_t sbase = smem_u32(smem);

    const int tid = threadIdx.x;
    const int l = tid & 31, wid = tid >> 5;
    const int mg = wid >> 2, nhq = wid & 3;
    const int rA = mg * 32 + (l >> 2);
    int rr[4];
    rr[0] = rA; rr[1] = rA + 8; rr[2] = rA + 16; rr[3] = rA + 24;
    const int colbq = nhq * 40;
    const int colt = (l & 3) * 2;
    const int pbase12 = nhq * 48 + (l & 3) * 12;
    const int m0 = blockIdx.x * TM;
    const int bb = blockIdx.x >> 2;

    const int lrow = mg * 32 + (l & 15);
    const int lcol = (l >> 4) * 8;
    const uint32_t aAp0 = sbase + OFF_EAA + (lrow * EAS + lcol) * 2;
    const uint32_t aAp1 = aAp0 + 16 * EAS * 2;
    const int sboff = nhq * 160 + l;

    const int grow = tid >> 2;
    const int gcb = (tid & 3) * 40;

    const u64 SC1  = packf2(2.0833333e-3f, 2.0833333e-3f);
    const u64 SC2  = packf2(-2.0833334e-2f, -2.0833334e-2f);
    const u64 SC3  = packf2(0.25f, 0.25f);
    const u64 SCH  = packf2(0.5f, 0.5f);
    const u64 C120 = packf2(8.3333333e-3f, 8.3333333e-3f);
    const u64 C24  = packf2(4.1666667e-2f, 4.1666667e-2f);
    const u64 C6   = packf2(1.6666667e-1f, 1.6666667e-1f);

    const uint2* buf0 = (const uint2*)(smem + OFF_BST) + sboff;
    const uint2* buf1 = (const uint2*)(smem + OFF_BST + CHKB) + sboff;

#define HBAR() asm volatile("bar.sync %0, 128;" :: "r"(1 + mg) : "memory")

#define PREF_CHUNK(cc, bufi) do {                                                \
    const uint4* gsrc = (const uint4*)g_Bfrag + (size_t)(cc) * 1600;             \
    const uint32_t dst = sbase + OFF_BST + (bufi) * CHKB;                        \
    for (int j = tid; j < 1600; j += NTH)                                        \
        cp_async16(dst + j * 16, gsrc + j);                                      \
} while (0)

#define PREF_PAR(ff) do {                                                        \
    const float4* psrc = (const float4*)g_Par + (size_t)(ff) * 320;              \
    const uint32_t pdst = sbase + OFF_PBUF + ((ff) % 3) * 5120;                  \
    for (int j = tid; j < 320; j += NTH)                                         \
        cp_async16(pdst + j * 16, psrc + j);                                     \
} while (0)

#define AGEN(ff, slot) do {                                                      \
    const float* pbn = (const float*)(smem + OFF_PBUF) + (slot) * 1280;          \
    const float xvg = xs[grow * XSTR + (ff)];                                    \
    const u64 xg2 = packf2(xvg, xvg);                                            \
    const u64* W1u = (const u64*)(pbn + gcb);                                    \
    const u64* b1u = (const u64*)(pbn + 160 + gcb);                              \
    uint4* eg = (uint4*)(eaA + grow * EAS + gcb);                                \
    _Pragma("unroll")                                                            \
    for (int q = 0; q < 5; ++q) {                                                \
        uint4 o;                                                                 \
        o.x = agen2(xg2, W1u[4 * q + 0], b1u[4 * q + 0], C120, C24, C6, SCH);    \
        o.y = agen2(xg2, W1u[4 * q + 1], b1u[4 * q + 1], C120, C24, C6, SCH);    \
        o.z = agen2(xg2, W1u[4 * q + 2], b1u[4 * q + 2], C120, C24, C6, SCH);    \
        o.w = agen2(xg2, W1u[4 * q + 3], b1u[4 * q + 3], C120, C24, C6, SCH);    \
        eg[q] = o;                                                               \
    }                                                                            \
} while (0)

/* full epilogue for feature fe using param slot slotE; consumes acc -> comb2 */
#define EPILOGUE(fe, slotE) do {                                                 \
    const float* pe = (const float*)(smem + OFF_PBUF) + (slotE) * 1280;          \
    float wbf = g_weights[bb * FF + (fe)];                                       \
    u64 xv2[4], nxv2[4], nc02[4], s1p[4], s2p[4];                                \
    float c0v[4];                                                                \
    _Pragma("unroll")                                                            \
    for (int ri = 0; ri < 4; ++ri) {                                             \
        float xv = xs[rr[ri] * XSTR + (fe)];                                     \
        float c0 = 0.5f * xv;                                                    \
        xv2[ri]  = packf2(xv, xv);                                               \
        nxv2[ri] = packf2(-xv, -xv);                                             \
        nc02[ri] = packf2(-c0, -c0);                                             \
        c0v[ri]  = c0;                                                           \
        s1p[ri] = 0ull; s2p[ri] = 0ull;                                          \
    }                                                                            \
    u64 featp[20];                                                               \
    {                                                                            \
        const u64* pB2 = (const u64*)(pe + 320 + pbase12);                       \
        const u64* pWg = (const u64*)(pe + 512 + pbase12);                       \
        const u64* pBg = (const u64*)(pe + 704 + pbase12);                       \
        _Pragma("unroll")                                                        \
        for (int jv = 0; jv < 5; ++jv) {                                         \
            u64 b2p = pB2[jv], wgp = pWg[jv], bgp = pBg[jv];                     \
            _Pragma("unroll")                                                    \
            for (int ri = 0; ri < 4; ++ri) {                                     \
                int idx = (jv * 2 + (ri >> 1)) * 4 + (ri & 1) * 2;               \
                u64 ap = packf2(acc[idx], acc[idx + 1]);                         \
                u64 a2; ADD2(a2, ap, b2p);                                       \
                u64 gz; FMA2(gz, xv2[ri], wgp, bgp);                             \
                u64 gv = fsig2(gz, SC1, SC2, SC3, SCH);                          \
                u64 dmx; ADD2(dmx, a2, nxv2[ri]);                                \
                u64 ft; FMA2(ft, gv, dmx, xv2[ri]);                              \
                featp[jv * 4 + ri] = ft;                                         \
                u64 d; ADD2(d, ft, nc02[ri]);                                    \
                ADD2(s1p[ri], s1p[ri], d);                                       \
                FMA2(s2p[ri], d, d, s2p[ri]);                                    \
            }                                                                    \
        }                                                                        \
    }                                                                            \
    float s1v[4], s2v[4];                                                        \
    _Pragma("unroll")                                                            \
    for (int ri = 0; ri < 4; ++ri) {                                             \
        float a_, b_;                                                            \
        unpackf2(a_, b_, s1p[ri]); s1v[ri] = a_ + b_;                            \
        unpackf2(a_, b_, s2p[ri]); s2v[ri] = a_ + b_;                            \
    }                                                                            \
    _Pragma("unroll")                                                            \
    for (int ri = 0; ri < 4; ++ri) {                                             \
        _Pragma("unroll")                                                        \
        for (int o = 1; o < 4; o <<= 1) {                                        \
            s1v[ri] += __shfl_xor_sync(0xffffffffu, s1v[ri], o);                 \
            s2v[ri] += __shfl_xor_sync(0xffffffffu, s2v[ri], o);                 \
        }                                                                        \
    }                                                                            \
    if ((l & 3) == 0) {                                                          \
        _Pragma("unroll")                                                        \
        for (int ri = 0; ri < 4; ++ri)                                           \
            *(float2*)(red + rr[ri] * 8 + nhq * 2) = make_float2(s1v[ri], s2v[ri]); \
    }                                                                            \
    HBAR();                                                                      \
    u64 inv2[4], nmi2[4];                                                        \
    _Pragma("unroll")                                                            \
    for (int ri = 0; ri < 4; ++ri) {                                             \
        float4 qa = *(const float4*)(red + rr[ri] * 8);                          \
        float4 qb = *(const float4*)(red + rr[ri] * 8 + 4);                      \
        float S1 = (qa.x + qa.z) + (qb.x + qb.z);                                \
        float S2 = (qa.y + qa.w) + (qb.y + qb.w);                                \
        float dm = S1 * (1.f / 160.f);                                           \
        float var = fmaf(-dm, dm, S2 * (1.f / 160.f));                           \
        float inv = rsqrtf(var + 1e-3f);                                         \
        float nmi = -(c0v[ri] + dm) * inv;                                       \
        inv2[ri] = packf2(inv, inv);                                             \
        nmi2[ri] = packf2(nmi, nmi);                                             \
    }                                                                            \
    {                                                                            \
        u64 wbf2 = packf2(wbf, wbf);                                             \
        const u64* pLg = (const u64*)(pe + 896 + pbase12);                       \
        const u64* pLb = (const u64*)(pe + 1088 + pbase12);                      \
        _Pragma("unroll")                                                        \
        for (int jv = 0; jv < 5; ++jv) {                                         \
            u64 lgp = pLg[jv], lbp = pLb[jv];                                    \
            _Pragma("unroll")                                                    \
            for (int ri = 0; ri < 4; ++ri) {                                     \
                u64 yt; FMA2(yt, featp[jv * 4 + ri], inv2[ri], nmi2[ri]);        \
                u64 y;  FMA2(y, yt, lgp, lbp);                                   \
                FMA2(comb2[jv * 4 + ri], wbf2, y, comb2[jv * 4 + ri]);           \
            }                                                                    \
        }                                                                        \
    }                                                                            \
} while (0)

    /* ------------------------------ preamble ------------------------------ */
    {
        const float4* xsrc = (const float4*)(x + (size_t)m0 * FF);
        for (int i = tid; i < TM * FF / 4; i += NTH) {
            float4 v = xsrc[i];
            float* d = xs + (i >> 3) * XSTR + ((i & 7) << 2);
            d[0] = v.x; d[1] = v.y; d[2] = v.z; d[3] = v.w;
        }
    }
    PREF_PAR(0);
    CP_COMMIT();
    u64 comb2[20];
#pragma unroll
    for (int i = 0; i < 20; ++i) comb2[i] = 0ull;
    CP_WAIT0();
    __syncthreads();

    float acc[40];

    /* ========================= phase 1: f loop ============================ */
    for (int f = 0; f < FF; ++f) {
        const int sc = f % 3;
        __syncthreads();   /* all warps past gemms of f-1; buffers + eaA free */
        PREF_CHUNK(2 * f, 0);
        if (f + 1 < FF) PREF_PAR(f + 1);
        CP_COMMIT();
        PREF_CHUNK(2 * f + 1, 1);
        CP_COMMIT();

        AGEN(f, sc);                    /* overlaps the in-flight DMA */
        if (f > 0) EPILOGUE(f - 1, (f - 1) % 3);

#pragma unroll
        for (int i = 0; i < 40; ++i) acc[i] = 0.f;
        CP_WAIT1();
        __syncthreads();               /* buf0 + params(f+1) + eaA published */
        gemm_chunk(acc, aAp0, aAp1, 0, buf0);
        CP_WAIT0();
        __syncthreads();               /* buf1 published */
        gemm_chunk(acc, aAp0, aAp1, 1, buf1);
    }

    /* ========================= phase 2: output MLP ======================== */
    __syncthreads();                   /* all past gemm(63) */
    PREF_CHUNK(64, 0); CP_COMMIT();
    PREF_CHUNK(65, 1); CP_COMMIT();
    EPILOGUE(31, 31 % 3);
    /* comb -> eaA (half-local rows; published by the CP sync below) */
#pragma unroll
    for (int jv = 0; jv < 5; ++jv)
#pragma unroll
        for (int ri = 0; ri < 4; ++ri) {
            float cx, cy;
            unpackf2(cx, cy, comb2[jv * 4 + ri]);
            *(uint32_t*)(eaA + rr[ri] * EAS + colbq + jv * 8 + colt) = pack_h2(cx, cy);
        }

    /* G1: h1 = elu(comb @ oW1 + ob1) */
#pragma unroll
    for (int i = 0; i < 40; ++i) acc[i] = 0.f;
    CP_WAIT1(); __syncthreads(); gemm_chunk(acc, aAp0, aAp1, 0, buf0);
    CP_WAIT0(); __syncthreads(); gemm_chunk(acc, aAp0, aAp1, 1, buf1);
    uint32_t h1p[20];
#pragma unroll
    for (int jv = 0; jv < 5; ++jv)
#pragma unroll
        for (int ri = 0; ri < 4; ++ri) {
            int idx = (jv * 2 + (ri >> 1)) * 4 + (ri & 1) * 2;
            int col = colbq + jv * 8 + colt;
            float2 vb = *(const float2*)(ob1 + col);
            h1p[jv * 4 + ri] =
                pack_h2(felu(acc[idx] + vb.x), felu(acc[idx + 1] + vb.y));
        }

    /* G3: og = sigmoid(comb @ oWg + obg) */
    __syncthreads();                   /* all past G1 gemms */
    PREF_CHUNK(66, 0); CP_COMMIT();
    PREF_CHUNK(67, 1); CP_COMMIT();
#pragma unroll
    for (int i = 0; i < 40; ++i) acc[i] = 0.f;
    CP_WAIT1(); __syncthreads(); gemm_chunk(acc, aAp0, aAp1, 0, buf0);
    CP_WAIT0(); __syncthreads(); gemm_chunk(acc, aAp0, aAp1, 1, buf1);
    u64 og2[20];
#pragma unroll
    for (int jv = 0; jv < 5; ++jv)
#pragma unroll
        for (int ri = 0; ri < 4; ++ri) {
            int idx = (jv * 2 + (ri >> 1)) * 4 + (ri & 1) * 2;
            int col = colbq + jv * 8 + colt;
            float2 vb = *(const float2*)(obg + col);
            og2[jv * 4 + ri] = packf2(fsigmoid(acc[idx] + vb.x),
                                      fsigmoid(acc[idx + 1] + vb.y));
        }

    /* G2: oa = h1 @ oW2 + ob2 */
    __syncthreads();                   /* all past G3 gemms; eaA free */
    PREF_CHUNK(68, 0); CP_COMMIT();
    PREF_CHUNK(69, 1); CP_COMMIT();
#pragma unroll
    for (int jv = 0; jv < 5; ++jv)
#pragma unroll
        for (int ri = 0; ri < 4; ++ri)
            *(uint32_t*)(eaA + rr[ri] * EAS + colbq + jv * 8 + colt) = h1p[jv * 4 + ri];
#pragma unroll
    for (int i = 0; i < 40; ++i) acc[i] = 0.f;
    CP_WAIT1(); __syncthreads(); gemm_chunk(acc, aAp0, aAp1, 0, buf0);
    CP_WAIT0(); __syncthreads(); gemm_chunk(acc, aAp0, aAp1, 1, buf1);

    /* combine + final LN + fragment-layout store */
    {
        u64 vp[20];
        float s1v[4] = {0.f, 0.f, 0.f, 0.f};
        float s2v[4] = {0.f, 0.f, 0.f, 0.f};
#pragma unroll
        for (int jv = 0; jv < 5; ++jv)
#pragma unroll
            for (int ri = 0; ri < 4; ++ri) {
                int idx = (jv * 2 + (ri >> 1)) * 4 + (ri & 1) * 2;
                int col = colbq + jv * 8 + colt;
                float2 vb = *(const float2*)(ob2 + col);
                float oax = acc[idx] + vb.x;
                float oay = acc[idx + 1] + vb.y;
                float ogx, ogy, cx, cy;
                unpackf2(ogx, ogy, og2[jv * 4 + ri]);
                unpackf2(cx, cy, comb2[jv * 4 + ri]);
                float vx = fmaf(ogx, oax - cx, cx);
                float vy = fmaf(ogy, oay - cy, cy);
                vp[jv * 4 + ri] = packf2(vx, vy);
                s1v[ri] += vx + vy;
                s2v[ri] = fmaf(vx, vx, s2v[ri]);
                s2v[ri] = fmaf(vy, vy, s2v[ri]);
            }
#pragma unroll
        for (int ri = 0; ri < 4; ++ri) {
#pragma unroll
            for (int o = 1; o < 4; o <<= 1) {
                s1v[ri] += __shfl_xor_sync(0xffffffffu, s1v[ri], o);
                s2v[ri] += __shfl_xor_sync(0xffffffffu, s2v[ri], o);
            }
        }
        if ((l & 3) == 0) {
#pragma unroll
            for (int ri = 0; ri < 4; ++ri)
                *(float2*)(red + rr[ri] * 8 + nhq * 2) = make_float2(s1v[ri], s2v[ri]);
        }
        HBAR();
        float meanv[4], invv[4];
#pragma unroll
        for (int ri = 0; ri < 4; ++ri) {
            float4 qa = *(const float4*)(red + rr[ri] * 8);
            float4 qb = *(const float4*)(red + rr[ri] * 8 + 4);
            float S1 = (qa.x + qa.z) + (qb.x + qb.z);
            float S2 = (qa.y + qa.w) + (qb.y + qb.w);
            float mean = S1 * (1.f / 160.f);
            float var = fmaf(-mean, mean, S2 * (1.f / 160.f));
            meanv[ri] = mean;
            invv[ri] = rsqrtf(var + 1e-3f);
        }
#pragma unroll
        for (int jv = 0; jv < 5; ++jv)
#pragma unroll
            for (int ri = 0; ri < 4; ++ri) {
                int col = colbq + jv * 8 + colt;
                float2 lg = *(const float2*)(olng + col);
                float2 lb = *(const float2*)(olnb + col);
                float vx, vy;
                unpackf2(vx, vy, vp[jv * 4 + ri]);
                float2 o;
                o.x = fmaf((vx - meanv[ri]) * invv[ri], lg.x, lb.x);
                o.y = fmaf((vy - meanv[ri]) * invv[ri], lg.y, lb.y);
                *(float2*)(out + (size_t)(m0 + rr[ri]) * HH + col) = o;
            }
    }
#undef HBAR
#undef AGEN
#undef EPILOGUE
#undef PREF_CHUNK
#undef PREF_PAR
}

/* --------------------------------- launch --------------------------------- */
extern "C" void kernel_launch(void* const* d_in, const int* in_sizes, int n_in,
                              void* d_out, int out_size) {
    const float* x    = (const float*)d_in[0];
    const float* W1   = (const float*)d_in[1];
    const float* b1   = (const float*)d_in[2];
    const float* W2   = (const float*)d_in[3];
    const float* b2   = (const float*)d_in[4];
    const float* Wg   = (const float*)d_in[5];
    const float* bg   = (const float*)d_in[6];
    const float* lng  = (const float*)d_in[7];
    const float* lnb  = (const float*)d_in[8];
    const float* Ww   = (const float*)d_in[9];
    const float* bw   = (const float*)d_in[10];
    const float* oW1  = (const float*)d_in[11];
    const float* ob1  = (const float*)d_in[12];
    const float* oW2  = (const float*)d_in[13];
    const float* ob2  = (const float*)d_in[14];
    const float* oWg  = (const float*)d_in[15];
    const float* obg  = (const float*)d_in[16];
    const float* olng = (const float*)d_in[17];
    const float* olnb = (const float*)d_in[18];
    float* out = (float*)d_out;

    const int pre_smem = HH * HH * (int)sizeof(float);   /* 102400 */
    cudaFuncSetAttribute(pre_kernel, cudaFuncAttributeMaxDynamicSharedMemorySize,
                         pre_smem);
    cudaFuncSetAttribute(fused_mma, cudaFuncAttributeMaxDynamicSharedMemorySize,
                         SMEM_TOTAL);

    pre_kernel<<<BB + 35, 256, pre_smem>>>(W2, oW1, oW2, oWg,
                                           W1, b1, b2, Wg, bg, lng, lnb,
                                           x, Ww, bw, out + (size_t)BB * TT * HH);
    fused_mma<<<(BB * TT) / TM, NTH, SMEM_TOTAL>>>(
        x, ob1, ob2, obg, olng, olnb, out);
}

// round 15
// speedup vs baseline: 1.2761x; 1.0642x over previous
#include <cuda_runtime.h>
#include <cuda_fp16.h>
#include <stdint.h>

#define FF 32
#define HH 160
#define BB 64
#define TT 256
#define TM 64
#define NTH 256
#define EAS 168      /* half stride for A images (>=160, ldmatrix-friendly) */
#define XSTR 33      /* x tile row stride (floats) */

typedef unsigned long long u64;

__device__ float g_weights[BB * FF];
/* B fragments: [t(35)][kt(10)][nt(20)][lane(32)] -> uint2 {b0,b1}
   tile slots: 0..31 = W2[f], 32 = oW1, 33 = oWg, 34 = oW2                    */
__device__ __align__(16) uint2 g_Bfrag[35 * 6400];
/* per-f parameter pack, 1280 floats per f:
   [0,160)=W1  [160,320)=b1  then 5 fragment-major arrays of 192 floats:
   b2@320, Wg@512, bg@704, lng@896, lnb@1088. */
__device__ __align__(16) float g_Par[FF * 1280];

/* ------------------------------ helpers ---------------------------------- */
__device__ __forceinline__ uint32_t smem_u32(const void* p) {
    uint32_t a;
    asm("{ .reg .u64 t; cvta.to.shared.u64 t, %1; cvt.u32.u64 %0, t; }" : "=r"(a) : "l"(p));
    return a;
}
__device__ __forceinline__ uint32_t pack_h2(float a, float b) {
    __half2 h = __floats2half2_rn(a, b);
    return *reinterpret_cast<uint32_t*>(&h);
}
__device__ __forceinline__ u64 packf2(float lo, float hi) {
    u64 r;
    asm("mov.b64 %0, {%1, %2};" : "=l"(r) : "f"(lo), "f"(hi));
    return r;
}
__device__ __forceinline__ void unpackf2(float& lo, float& hi, u64 v) {
    asm("mov.b64 {%0, %1}, %2;" : "=f"(lo), "=f"(hi) : "l"(v));
}
#define FMA2(d, a, b, c) asm("fma.rn.f32x2 %0, %1, %2, %3;" : "=l"(d) : "l"(a), "l"(b), "l"(c))
#define ADD2(d, a, b)    asm("add.rn.f32x2 %0, %1, %2;" : "=l"(d) : "l"(a), "l"(b))
#define MUL2(d, a, b)    asm("mul.rn.f32x2 %0, %1, %2;" : "=l"(d) : "l"(a), "l"(b))

__device__ __forceinline__ u64 fsig2(u64 z, u64 SC1, u64 SC2, u64 SC3, u64 SCH) {
    u64 z2, t;
    MUL2(z2, z, z);
    FMA2(t, z2, SC1, SC2);
    FMA2(t, z2, t, SC3);
    FMA2(t, z, t, SCH);
    return t;
}
__device__ __forceinline__ uint32_t agen2(u64 xg2, u64 w, u64 b,
                                          u64 C120, u64 C24, u64 C6, u64 SCH) {
    u64 z, z2, qq, p;
    FMA2(z, xg2, w, b);
    MUL2(z2, z, z);
    FMA2(qq, z, C120, C24);
    FMA2(qq, z, qq, C6);
    FMA2(qq, z, qq, SCH);
    FMA2(p, z2, qq, z);
    float zl, zh, pl, ph;
    unpackf2(zl, zh, z);
    unpackf2(pl, ph, p);
    float rl = zl > 0.f ? zl : pl;
    float rh = zh > 0.f ? zh : ph;
    return pack_h2(rl, rh);
}
__device__ __forceinline__ float fsigmoid(float z) {
    float z2 = z * z;
    float t = fmaf(z2, 2.0833333e-3f, -2.0833334e-2f);
    t = fmaf(z2, t, 0.25f);
    return fmaf(z, t, 0.5f);
}
__device__ __forceinline__ float felu(float z) {
    float p = fmaf(z, 8.3333333e-3f, 4.1666667e-2f);
    p = fmaf(z, p, 1.6666667e-1f);
    p = fmaf(z, p, 0.5f);
    p = fmaf(z, p, 1.0f);
    p = z * p;
    return z > 0.f ? z : p;
}
__device__ __forceinline__ void mma16816(float* c, uint32_t a0, uint32_t a1,
                                         uint32_t a2, uint32_t a3,
                                         uint32_t b0, uint32_t b1) {
    asm volatile(
        "mma.sync.aligned.m16n8k16.row.col.f32.f16.f16.f32 "
        "{%0,%1,%2,%3}, {%4,%5,%6,%7}, {%8,%9}, {%0,%1,%2,%3};"
        : "+f"(c[0]), "+f"(c[1]), "+f"(c[2]), "+f"(c[3])
        : "r"(a0), "r"(a1), "r"(a2), "r"(a3), "r"(b0), "r"(b1));
}
__device__ __forceinline__ void cp_async16(uint32_t saddr, const void* gptr) {
    asm volatile("cp.async.cg.shared.global [%0], [%1], 16;" :: "r"(saddr), "l"(gptr));
}
#define CP_COMMIT() asm volatile("cp.async.commit_group;" ::: "memory")
#define CP_WAIT0()  asm volatile("cp.async.wait_group 0;" ::: "memory")
#define CP_WAIT1()  asm volatile("cp.async.wait_group 1;" ::: "memory")
#define LDMX4(a0, a1, a2, a3, p)                                                 \
    asm volatile("ldmatrix.sync.aligned.m8n8.x4.shared.b16 {%0,%1,%2,%3}, [%4];" \
                 : "=r"(a0), "=r"(a1), "=r"(a2), "=r"(a3) : "r"(p))

/* gemm chunk: 5 k-tiles, 2 m-tiles per warp, B from smem stage */
__device__ __forceinline__ void gemm_chunk(float* acc, uint32_t ap0, uint32_t ap1,
                                           int h, const uint2* sb) {
#pragma unroll
    for (int kt = 0; kt < 5; ++kt) {
        uint32_t a0, a1, a2, a3, c0, c1, c2, c3;
        LDMX4(a0, a1, a2, a3, ap0 + (h * 5 + kt) * 32);
        LDMX4(c0, c1, c2, c3, ap1 + (h * 5 + kt) * 32);
#pragma unroll
        for (int j = 0; j < 5; ++j) {
            uint2 bv = sb[(kt * 20 + j) * 32];
            mma16816(acc + (j * 2 + 0) * 4, a0, a1, a2, a3, bv.x, bv.y);
            mma16816(acc + (j * 2 + 1) * 4, c0, c1, c2, c3, bv.x, bv.y);
        }
    }
}

/* --------------- kernel 0: merged prep (B fragments + params) + weights ---
   512 threads/block.
   blocks [0,64): selection weights (16 row-groups x 32 cols, 4 accumulators)
   blocks [64,99): per-tile fragment conversion via smem staging             */
__global__ void pre_kernel(const float* __restrict__ W2,
                           const float* __restrict__ oW1,
                           const float* __restrict__ oW2,
                           const float* __restrict__ oWg,
                           const float* __restrict__ W1,
                           const float* __restrict__ b1,
                           const float* __restrict__ b2,
                           const float* __restrict__ Wg,
                           const float* __restrict__ bg,
                           const float* __restrict__ lng,
                           const float* __restrict__ lnb,
                           const float* __restrict__ x,
                           const float* __restrict__ Ww,
                           const float* __restrict__ bw,
                           float* __restrict__ out_tail) {
    extern __shared__ float stile[];   /* 160x160 fp32 = 102400 B (conv blocks) */
    if (blockIdx.x >= BB) {
        int t = blockIdx.x - BB;   /* 0..34 */
        const float* src = (t < 32) ? (W2 + (size_t)t * HH * HH)
                                    : (t == 32 ? oW1 : (t == 33 ? oWg : oW2));
        /* stage tile coalesced */
        {
            const float4* s4 = (const float4*)src;
            float4* d4 = (float4*)stile;
            for (int i = threadIdx.x; i < HH * HH / 4; i += blockDim.x)
                d4[i] = s4[i];
        }
        __syncthreads();
        /* fragment conversion: scattered smem reads, coalesced gmem writes */
        for (int idx = threadIdx.x; idx < 6400; idx += blockDim.x) {
            int kt = idx / 640;
            int nt = (idx / 32) % 20;
            int l  = idx & 31;
            int k0 = kt * 16 + (l & 3) * 2;
            int n  = nt * 8 + (l >> 2);
            uint2 v;
            v.x = pack_h2(stile[k0 * HH + n],       stile[(k0 + 1) * HH + n]);
            v.y = pack_h2(stile[(k0 + 8) * HH + n], stile[(k0 + 9) * HH + n]);
            g_Bfrag[(size_t)t * 6400 + idx] = v;
        }
        /* per-f parameter pack (fragment-major layout) */
        if (t < FF) {
            const float* srcs[7] = { W1 + t * HH, b1 + t * HH, b2 + t * HH,
                                     Wg + t * HH, bg + t * HH,
                                     lng + t * HH, lnb + t * HH };
            for (int jl = threadIdx.x; jl < 1120; jl += blockDim.x) {
                int a = jl / 160, c = jl - a * 160;
                int p;
                if (a < 2) {
                    p = a * 160 + c;
                } else {
                    int g = c / 40, rem = c - g * 40;
                    int j = rem >> 3, tt = (rem >> 1) & 3, e = rem & 1;
                    p = 320 + (a - 2) * 192 + g * 48 + tt * 12 + j * 2 + e;
                }
                g_Par[t * 1280 + p] = srcs[a][c];
            }
        }
        return;
    }
    /* selection weights: 16 row-groups, 4 accumulators, MLP ~16 */
    int b = blockIdx.x;
    int tid = threadIdx.x;
    int c = tid & 31, g = tid >> 5;   /* g in 0..15 */
    const float* xb = x + b * (TT * FF);
    float a0 = 0.f, a1 = 0.f, a2 = 0.f, a3 = 0.f;
#pragma unroll 4
    for (int i = 0; i < TT * FF; i += 64) {
        int r = g + i;
        a0 = fmaf(xb[r],      Ww[r * FF + c],        a0);
        a1 = fmaf(xb[r + 16], Ww[(r + 16) * FF + c], a1);
        a2 = fmaf(xb[r + 32], Ww[(r + 32) * FF + c], a2);
        a3 = fmaf(xb[r + 48], Ww[(r + 48) * FF + c], a3);
    }
    float acc = (a0 + a1) + (a2 + a3);
    __shared__ float red[16][32];
    red[g][c] = acc;
    __syncthreads();
    if (tid < 32) {
        float s = 0.f;
#pragma unroll
        for (int i = 0; i < 16; ++i) s += red[i][tid];
        s += bw[tid];
        float m = s;
#pragma unroll
        for (int o = 16; o; o >>= 1) m = fmaxf(m, __shfl_xor_sync(0xffffffffu, m, o));
        float e = expf(s - m);
        float se = e;
#pragma unroll
        for (int o = 16; o; o >>= 1) se += __shfl_xor_sync(0xffffffffu, se, o);
        float w = e / se;
        g_weights[b * 32 + tid] = w;
        out_tail[b * 32 + tid] = w;
    }
}

/* ------------------------- kernel 1: fused VSN (HMMA) ---------------------
   (identical to the round-12/14 kernel)
   SMEM (bytes):
     xs      [0,       8448)   64 x 33 fp32
     eaA     [8448,   29952)   64 x 168 fp16
     red     [29952,  32000)   64 x 8 fp32
     pbuf    [32000,  47360)   3 x 5120 param ring
     Bstage  [47360,  98560)   2 x 25600 cp.async double buffer              */
#define OFF_EAA  8448
#define OFF_RED  29952
#define OFF_PBUF 32000
#define OFF_BST  47360
#define CHKB     25600
#define SMEM_TOTAL 98560

__global__ void __launch_bounds__(NTH, 2)
fused_mma(const float* __restrict__ x,
          const float* __restrict__ ob1, const float* __restrict__ ob2,
          const float* __restrict__ obg,
          const float* __restrict__ olng, const float* __restrict__ olnb,
          float* __restrict__ out) {
    extern __shared__ char smem[];
    float*  xs  = (float*)smem;
    __half* eaA = (__half*)(smem + OFF_EAA);
    float*  red = (float*)(smem + OFF_RED);
    const uint32_t sbase = smem_u32(smem);

    const int tid = threadIdx.x;
    const int l = tid & 31, wid = tid >> 5;
    const int mg = wid >> 2, nhq = wid & 3;
    const int rA = mg * 32 + (l >> 2);
    int rr[4];
    rr[0] = rA; rr[1] = rA + 8; rr[2] = rA + 16; rr[3] = rA + 24;
    const int colbq = nhq * 40;
    const int colt = (l & 3) * 2;
    const int pbase12 = nhq * 48 + (l & 3) * 12;
    const int m0 = blockIdx.x * TM;
    const int bb = blockIdx.x >> 2;

    const int lrow = mg * 32 + (l & 15);
    const int lcol = (l >> 4) * 8;
    const uint32_t aAp0 = sbase + OFF_EAA + (lrow * EAS + lcol) * 2;
    const uint32_t aAp1 = aAp0 + 16 * EAS * 2;
    const int sboff = nhq * 160 + l;

    const int grow = tid >> 2;
    const int gcb = (tid & 3) * 40;

    const u64 SC1  = packf2(2.0833333e-3f, 2.0833333e-3f);
    const u64 SC2  = packf2(-2.0833334e-2f, -2.0833334e-2f);
    const u64 SC3  = packf2(0.25f, 0.25f);
    const u64 SCH  = packf2(0.5f, 0.5f);
    const u64 C120 = packf2(8.3333333e-3f, 8.3333333e-3f);
    const u64 C24  = packf2(4.1666667e-2f, 4.1666667e-2f);
    const u64 C6   = packf2(1.6666667e-1f, 1.6666667e-1f);

    const uint2* buf0 = (const uint2*)(smem + OFF_BST) + sboff;
    const uint2* buf1 = (const uint2*)(smem + OFF_BST + CHKB) + sboff;

#define HBAR() asm volatile("bar.sync %0, 128;" :: "r"(1 + mg) : "memory")

#define PREF_CHUNK(cc, bufi) do {                                                \
    const uint4* gsrc = (const uint4*)g_Bfrag + (size_t)(cc) * 1600;             \
    const uint32_t dst = sbase + OFF_BST + (bufi) * CHKB;                        \
    for (int j = tid; j < 1600; j += NTH)                                        \
        cp_async16(dst + j * 16, gsrc + j);                                      \
} while (0)

#define PREF_PAR(ff) do {                                                        \
    const float4* psrc = (const float4*)g_Par + (size_t)(ff) * 320;              \
    const uint32_t pdst = sbase + OFF_PBUF + ((ff) % 3) * 5120;                  \
    for (int j = tid; j < 320; j += NTH)                                         \
        cp_async16(pdst + j * 16, psrc + j);                                     \
} while (0)

#define AGEN(ff, slot) do {                                                      \
    const float* pbn = (const float*)(smem + OFF_PBUF) + (slot) * 1280;          \
    const float xvg = xs[grow * XSTR + (ff)];                                    \
    const u64 xg2 = packf2(xvg, xvg);                                            \
    const u64* W1u = (const u64*)(pbn + gcb);                                    \
    const u64* b1u = (const u64*)(pbn + 160 + gcb);                              \
    uint4* eg = (uint4*)(eaA + grow * EAS + gcb);                                \
    _Pragma("unroll")                                                            \
    for (int q = 0; q < 5; ++q) {                                                \
        uint4 o;                                                                 \
        o.x = agen2(xg2, W1u[4 * q + 0], b1u[4 * q + 0], C120, C24, C6, SCH);    \
        o.y = agen2(xg2, W1u[4 * q + 1], b1u[4 * q + 1], C120, C24, C6, SCH);    \
        o.z = agen2(xg2, W1u[4 * q + 2], b1u[4 * q + 2], C120, C24, C6, SCH);    \
        o.w = agen2(xg2, W1u[4 * q + 3], b1u[4 * q + 3], C120, C24, C6, SCH);    \
        eg[q] = o;                                                               \
    }                                                                            \
} while (0)

/* full epilogue for feature fe using param slot slotE; consumes acc -> comb2 */
#define EPILOGUE(fe, slotE) do {                                                 \
    const float* pe = (const float*)(smem + OFF_PBUF) + (slotE) * 1280;          \
    float wbf = g_weights[bb * FF + (fe)];                                       \
    u64 xv2[4], nxv2[4], nc02[4], s1p[4], s2p[4];                                \
    float c0v[4];                                                                \
    _Pragma("unroll")                                                            \
    for (int ri = 0; ri < 4; ++ri) {                                             \
        float xv = xs[rr[ri] * XSTR + (fe)];                                     \
        float c0 = 0.5f * xv;                                                    \
        xv2[ri]  = packf2(xv, xv);                                               \
        nxv2[ri] = packf2(-xv, -xv);                                             \
        nc02[ri] = packf2(-c0, -c0);                                             \
        c0v[ri]  = c0;                                                           \
        s1p[ri] = 0ull; s2p[ri] = 0ull;                                          \
    }                                                                            \
    u64 featp[20];                                                               \
    {                                                                            \
        const u64* pB2 = (const u64*)(pe + 320 + pbase12);                       \
        const u64* pWg = (const u64*)(pe + 512 + pbase12);                       \
        const u64* pBg = (const u64*)(pe + 704 + pbase12);                       \
        _Pragma("unroll")                                                        \
        for (int jv = 0; jv < 5; ++jv) {                                         \
            u64 b2p = pB2[jv], wgp = pWg[jv], bgp = pBg[jv];                     \
            _Pragma("unroll")                                                    \
            for (int ri = 0; ri < 4; ++ri) {                                     \
                int idx = (jv * 2 + (ri >> 1)) * 4 + (ri & 1) * 2;               \
                u64 ap = packf2(acc[idx], acc[idx + 1]);                         \
                u64 a2; ADD2(a2, ap, b2p);                                       \
                u64 gz; FMA2(gz, xv2[ri], wgp, bgp);                             \
                u64 gv = fsig2(gz, SC1, SC2, SC3, SCH);                          \
                u64 dmx; ADD2(dmx, a2, nxv2[ri]);                                \
                u64 ft; FMA2(ft, gv, dmx, xv2[ri]);                              \
                featp[jv * 4 + ri] = ft;                                         \
                u64 d; ADD2(d, ft, nc02[ri]);                                    \
                ADD2(s1p[ri], s1p[ri], d);                                       \
                FMA2(s2p[ri], d, d, s2p[ri]);                                    \
            }                                                                    \
        }                                                                        \
    }                                                                            \
    float s1v[4], s2v[4];                                                        \
    _Pragma("unroll")                                                            \
    for (int ri = 0; ri < 4; ++ri) {                                             \
        float a_, b_;                                                            \
        unpackf2(a_, b_, s1p[ri]); s1v[ri] = a_ + b_;                            \
        unpackf2(a_, b_, s2p[ri]); s2v[ri] = a_ + b_;                            \
    }                                                                            \
    _Pragma("unroll")                                                            \
    for (int ri = 0; ri < 4; ++ri) {                                             \
        _Pragma("unroll")                                                        \
        for (int o = 1; o < 4; o <<= 1) {                                        \
            s1v[ri] += __shfl_xor_sync(0xffffffffu, s1v[ri], o);                 \
            s2v[ri] += __shfl_xor_sync(0xffffffffu, s2v[ri], o);                 \
        }                                                                        \
    }                                                                            \
    if ((l & 3) == 0) {                                                          \
        _Pragma("unroll")                                                        \
        for (int ri = 0; ri < 4; ++ri)                                           \
            *(float2*)(red + rr[ri] * 8 + nhq * 2) = make_float2(s1v[ri], s2v[ri]); \
    }                                                                            \
    HBAR();                                                                      \
    u64 inv2[4], nmi2[4];                                                        \
    _Pragma("unroll")                                                            \
    for (int ri = 0; ri < 4; ++ri) {                                             \
        float4 qa = *(const float4*)(red + rr[ri] * 8);                          \
        float4 qb = *(const float4*)(red + rr[ri] * 8 + 4);                      \
        float S1 = (qa.x + qa.z) + (qb.x + qb.z);                                \
        float S2 = (qa.y + qa.w) + (qb.y + qb.w);                                \
        float dm = S1 * (1.f / 160.f);                                           \
        float var = fmaf(-dm, dm, S2 * (1.f / 160.f));                           \
        float inv = rsqrtf(var + 1e-3f);                                         \
        float nmi = -(c0v[ri] + dm) * inv;                                       \
        inv2[ri] = packf2(inv, inv);                                             \
        nmi2[ri] = packf2(nmi, nmi);                                             \
    }                                                                            \
    {                                                                            \
        u64 wbf2 = packf2(wbf, wbf);                                             \
        const u64* pLg = (const u64*)(pe + 896 + pbase12);                       \
        const u64* pLb = (const u64*)(pe + 1088 + pbase12);                      \
        _Pragma("unroll")                                                        \
        for (int jv = 0; jv < 5; ++jv) {                                         \
            u64 lgp = pLg[jv], lbp = pLb[jv];                                    \
            _Pragma("unroll")                                                    \
            for (int ri = 0; ri < 4; ++ri) {                                     \
                u64 yt; FMA2(yt, featp[jv * 4 + ri], inv2[ri], nmi2[ri]);        \
                u64 y;  FMA2(y, yt, lgp, lbp);                                   \
                FMA2(comb2[jv * 4 + ri], wbf2, y, comb2[jv * 4 + ri]);           \
            }                                                                    \
        }                                                                        \
    }                                                                            \
} while (0)

    /* ------------------------------ preamble ------------------------------ */
    {
        const float4* xsrc = (const float4*)(x + (size_t)m0 * FF);
        for (int i = tid; i < TM * FF / 4; i += NTH) {
            float4 v = xsrc[i];
            float* d = xs + (i >> 3) * XSTR + ((i & 7) << 2);
            d[0] = v.x; d[1] = v.y; d[2] = v.z; d[3] = v.w;
        }
    }
    PREF_PAR(0);
    CP_COMMIT();
    u64 comb2[20];
#pragma unroll
    for (int i = 0; i < 20; ++i) comb2[i] = 0ull;
    CP_WAIT0();
    __syncthreads();

    float acc[40];

    /* ========================= phase 1: f loop ============================ */
    for (int f = 0; f < FF; ++f) {
        const int sc = f % 3;
        __syncthreads();   /* all warps past gemms of f-1; buffers + eaA free */
        PREF_CHUNK(2 * f, 0);
        if (f + 1 < FF) PREF_PAR(f + 1);
        CP_COMMIT();
        PREF_CHUNK(2 * f + 1, 1);
        CP_COMMIT();

        AGEN(f, sc);                    /* overlaps the in-flight DMA */
        if (f > 0) EPILOGUE(f - 1, (f - 1) % 3);

#pragma unroll
        for (int i = 0; i < 40; ++i) acc[i] = 0.f;
        CP_WAIT1();
        __syncthreads();               /* buf0 + params(f+1) + eaA published */
        gemm_chunk(acc, aAp0, aAp1, 0, buf0);
        CP_WAIT0();
        __syncthreads();               /* buf1 published */
        gemm_chunk(acc, aAp0, aAp1, 1, buf1);
    }

    /* ========================= phase 2: output MLP ======================== */
    __syncthreads();                   /* all past gemm(63) */
    PREF_CHUNK(64, 0); CP_COMMIT();
    PREF_CHUNK(65, 1); CP_COMMIT();
    EPILOGUE(31, 31 % 3);
    /* comb -> eaA (half-local rows; published by the CP sync below) */
#pragma unroll
    for (int jv = 0; jv < 5; ++jv)
#pragma unroll
        for (int ri = 0; ri < 4; ++ri) {
            float cx, cy;
            unpackf2(cx, cy, comb2[jv * 4 + ri]);
            *(uint32_t*)(eaA + rr[ri] * EAS + colbq + jv * 8 + colt) = pack_h2(cx, cy);
        }

    /* G1: h1 = elu(comb @ oW1 + ob1) */
#pragma unroll
    for (int i = 0; i < 40; ++i) acc[i] = 0.f;
    CP_WAIT1(); __syncthreads(); gemm_chunk(acc, aAp0, aAp1, 0, buf0);
    CP_WAIT0(); __syncthreads(); gemm_chunk(acc, aAp0, aAp1, 1, buf1);
    uint32_t h1p[20];
#pragma unroll
    for (int jv = 0; jv < 5; ++jv)
#pragma unroll
        for (int ri = 0; ri < 4; ++ri) {
            int idx = (jv * 2 + (ri >> 1)) * 4 + (ri & 1) * 2;
            int col = colbq + jv * 8 + colt;
            float2 vb = *(const float2*)(ob1 + col);
            h1p[jv * 4 + ri] =
                pack_h2(felu(acc[idx] + vb.x), felu(acc[idx + 1] + vb.y));
        }

    /* G3: og = sigmoid(comb @ oWg + obg) */
    __syncthreads();                   /* all past G1 gemms */
    PREF_CHUNK(66, 0); CP_COMMIT();
    PREF_CHUNK(67, 1); CP_COMMIT();
#pragma unroll
    for (int i = 0; i < 40; ++i) acc[i] = 0.f;
    CP_WAIT1(); __syncthreads(); gemm_chunk(acc, aAp0, aAp1, 0, buf0);
    CP_WAIT0(); __syncthreads(); gemm_chunk(acc, aAp0, aAp1, 1, buf1);
    u64 og2[20];
#pragma unroll
    for (int jv = 0; jv < 5; ++jv)
#pragma unroll
        for (int ri = 0; ri < 4; ++ri) {
            int idx = (jv * 2 + (ri >> 1)) * 4 + (ri & 1) * 2;
            int col = colbq + jv * 8 + colt;
            float2 vb = *(const float2*)(obg + col);
            og2[jv * 4 + ri] = packf2(fsigmoid(acc[idx] + vb.x),
                                      fsigmoid(acc[idx + 1] + vb.y));
        }

    /* G2: oa = h1 @ oW2 + ob2 */
    __syncthreads();                   /* all past G3 gemms; eaA free */
    PREF_CHUNK(68, 0); CP_COMMIT();
    PREF_CHUNK(69, 1); CP_COMMIT();
#pragma unroll
    for (int jv = 0; jv < 5; ++jv)
#pragma unroll
        for (int ri = 0; ri < 4; ++ri)
            *(uint32_t*)(eaA + rr[ri] * EAS + colbq + jv * 8 + colt) = h1p[jv * 4 + ri];
#pragma unroll
    for (int i = 0; i < 40; ++i) acc[i] = 0.f;
    CP_WAIT1(); __syncthreads(); gemm_chunk(acc, aAp0, aAp1, 0, buf0);
    CP_WAIT0(); __syncthreads(); gemm_chunk(acc, aAp0, aAp1, 1, buf1);

    /* combine + final LN + fragment-layout store */
    {
        u64 vp[20];
        float s1v[4] = {0.f, 0.f, 0.f, 0.f};
        float s2v[4] = {0.f, 0.f, 0.f, 0.f};
#pragma unroll
        for (int jv = 0; jv < 5; ++jv)
#pragma unroll
            for (int ri = 0; ri < 4; ++ri) {
                int idx = (jv * 2 + (ri >> 1)) * 4 + (ri & 1) * 2;
                int col = colbq + jv * 8 + colt;
                float2 vb = *(const float2*)(ob2 + col);
                float oax = acc[idx] + vb.x;
                float oay = acc[idx + 1] + vb.y;
                float ogx, ogy, cx, cy;
                unpackf2(ogx, ogy, og2[jv * 4 + ri]);
                unpackf2(cx, cy, comb2[jv * 4 + ri]);
                float vx = fmaf(ogx, oax - cx, cx);
                float vy = fmaf(ogy, oay - cy, cy);
                vp[jv * 4 + ri] = packf2(vx, vy);
                s1v[ri] += vx + vy;
                s2v[ri] = fmaf(vx, vx, s2v[ri]);
                s2v[ri] = fmaf(vy, vy, s2v[ri]);
            }
#pragma unroll
        for (int ri = 0; ri < 4; ++ri) {
#pragma unroll
            for (int o = 1; o < 4; o <<= 1) {
                s1v[ri] += __shfl_xor_sync(0xffffffffu, s1v[ri], o);
                s2v[ri] += __shfl_xor_sync(0xffffffffu, s2v[ri], o);
            }
        }
        if ((l & 3) == 0) {
#pragma unroll
            for (int ri = 0; ri < 4; ++ri)
                *(float2*)(red + rr[ri] * 8 + nhq * 2) = make_float2(s1v[ri], s2v[ri]);
        }
        HBAR();
        float meanv[4], invv[4];
#pragma unroll
        for (int ri = 0; ri < 4; ++ri) {
            float4 qa = *(const float4*)(red + rr[ri] * 8);
            float4 qb = *(const float4*)(red + rr[ri] * 8 + 4);
            float S1 = (qa.x + qa.z) + (qb.x + qb.z);
            float S2 = (qa.y + qa.w) + (qb.y + qb.w);
            float mean = S1 * (1.f / 160.f);
            float var = fmaf(-mean, mean, S2 * (1.f / 160.f));
            meanv[ri] = mean;
            invv[ri] = rsqrtf(var + 1e-3f);
        }
#pragma unroll
        for (int jv = 0; jv < 5; ++jv)
#pragma unroll
            for (int ri = 0; ri < 4; ++ri) {
                int col = colbq + jv * 8 + colt;
                float2 lg = *(const float2*)(olng + col);
                float2 lb = *(const float2*)(olnb + col);
                float vx, vy;
                unpackf2(vx, vy, vp[jv * 4 + ri]);
                float2 o;
                o.x = fmaf((vx - meanv[ri]) * invv[ri], lg.x, lb.x);
                o.y = fmaf((vy - meanv[ri]) * invv[ri], lg.y, lb.y);
                *(float2*)(out + (size_t)(m0 + rr[ri]) * HH + col) = o;
            }
    }
#undef HBAR
#undef AGEN
#undef EPILOGUE
#undef PREF_CHUNK
#undef PREF_PAR
}

/* --------------------------------- launch --------------------------------- */
extern "C" void kernel_launch(void* const* d_in, const int* in_sizes, int n_in,
                              void* d_out, int out_size) {
    const float* x    = (const float*)d_in[0];
    const float* W1   = (const float*)d_in[1];
    const float* b1   = (const float*)d_in[2];
    const float* W2   = (const float*)d_in[3];
    const float* b2   = (const float*)d_in[4];
    const float* Wg   = (const float*)d_in[5];
    const float* bg   = (const float*)d_in[6];
    const float* lng  = (const float*)d_in[7];
    const float* lnb  = (const float*)d_in[8];
    const float* Ww   = (const float*)d_in[9];
    const float* bw   = (const float*)d_in[10];
    const float* oW1  = (const float*)d_in[11];
    const float* ob1  = (const float*)d_in[12];
    const float* oW2  = (const float*)d_in[13];
    const float* ob2  = (const float*)d_in[14];
    const float* oWg  = (const float*)d_in[15];
    const float* obg  = (const float*)d_in[16];
    const float* olng = (const float*)d_in[17];
    const float* olnb = (const float*)d_in[18];
    float* out = (float*)d_out;

    const int pre_smem = HH * HH * (int)sizeof(float);   /* 102400 */
    cudaFuncSetAttribute(pre_kernel, cudaFuncAttributeMaxDynamicSharedMemorySize,
                         pre_smem);
    cudaFuncSetAttribute(fused_mma, cudaFuncAttributeMaxDynamicSharedMemorySize,
                         SMEM_TOTAL);

    pre_kernel<<<BB + 35, 512, pre_smem>>>(W2, oW1, oW2, oWg,
                                           W1, b1, b2, Wg, bg, lng, lnb,
                                           x, Ww, bw, out + (size_t)BB * TT * HH);
    fused_mma<<<(BB * TT) / TM, NTH, SMEM_TOTAL>>>(
        x, ob1, ob2, obg, olng, olnb, out);
}

// round 16
// speedup vs baseline: 1.2764x; 1.0002x over previous
#include <cuda_runtime.h>
#include <cuda_fp16.h>
#include <stdint.h>

#define FF 32
#define HH 160
#define BB 64
#define TT 256
#define TM 64
#define NTH 256
#define EAS 168      /* half stride for A images (>=160, ldmatrix-friendly) */
#define XSTR 33      /* x tile row stride (floats) */

typedef unsigned long long u64;

__device__ float g_weights[BB * FF];
/* B fragments, LDS.128-friendly layout:
   per tile t (0..34): 10 kt x 4 nhq x 1280 B blocks.
   block (kt,nhq): [0,512) = n-tiles j0,j1 interleaved as uint4 per lane,
                   [512,1024) = j2,j3, [1024,1280) = j4 as uint2 per lane.
   tile slots: 0..31 = W2[f], 32 = oW1, 33 = oWg, 34 = oW2                    */
__device__ __align__(16) uint2 g_Bfrag[35 * 6400];
/* per-f parameter pack, 1280 floats per f:
   [0,160)=W1  [160,320)=b1  then 5 fragment-major arrays of 192 floats:
   b2@320, Wg@512, bg@704, lng@896, lnb@1088. */
__device__ __align__(16) float g_Par[FF * 1280];

/* ------------------------------ helpers ---------------------------------- */
__device__ __forceinline__ uint32_t smem_u32(const void* p) {
    uint32_t a;
    asm("{ .reg .u64 t; cvta.to.shared.u64 t, %1; cvt.u32.u64 %0, t; }" : "=r"(a) : "l"(p));
    return a;
}
__device__ __forceinline__ uint32_t pack_h2(float a, float b) {
    __half2 h = __floats2half2_rn(a, b);
    return *reinterpret_cast<uint32_t*>(&h);
}
__device__ __forceinline__ u64 packf2(float lo, float hi) {
    u64 r;
    asm("mov.b64 %0, {%1, %2};" : "=l"(r) : "f"(lo), "f"(hi));
    return r;
}
__device__ __forceinline__ void unpackf2(float& lo, float& hi, u64 v) {
    asm("mov.b64 {%0, %1}, %2;" : "=f"(lo), "=f"(hi) : "l"(v));
}
#define FMA2(d, a, b, c) asm("fma.rn.f32x2 %0, %1, %2, %3;" : "=l"(d) : "l"(a), "l"(b), "l"(c))
#define ADD2(d, a, b)    asm("add.rn.f32x2 %0, %1, %2;" : "=l"(d) : "l"(a), "l"(b))
#define MUL2(d, a, b)    asm("mul.rn.f32x2 %0, %1, %2;" : "=l"(d) : "l"(a), "l"(b))

__device__ __forceinline__ u64 fsig2(u64 z, u64 SC1, u64 SC2, u64 SC3, u64 SCH) {
    u64 z2, t;
    MUL2(z2, z, z);
    FMA2(t, z2, SC1, SC2);
    FMA2(t, z2, t, SC3);
    FMA2(t, z, t, SCH);
    return t;
}
__device__ __forceinline__ uint32_t agen2(u64 xg2, u64 w, u64 b,
                                          u64 C120, u64 C24, u64 C6, u64 SCH) {
    u64 z, z2, qq, p;
    FMA2(z, xg2, w, b);
    MUL2(z2, z, z);
    FMA2(qq, z, C120, C24);
    FMA2(qq, z, qq, C6);
    FMA2(qq, z, qq, SCH);
    FMA2(p, z2, qq, z);
    float zl, zh, pl, ph;
    unpackf2(zl, zh, z);
    unpackf2(pl, ph, p);
    float rl = zl > 0.f ? zl : pl;
    float rh = zh > 0.f ? zh : ph;
    return pack_h2(rl, rh);
}
__device__ __forceinline__ float fsigmoid(float z) {
    float z2 = z * z;
    float t = fmaf(z2, 2.0833333e-3f, -2.0833334e-2f);
    t = fmaf(z2, t, 0.25f);
    return fmaf(z, t, 0.5f);
}
__device__ __forceinline__ float felu(float z) {
    float p = fmaf(z, 8.3333333e-3f, 4.1666667e-2f);
    p = fmaf(z, p, 1.6666667e-1f);
    p = fmaf(z, p, 0.5f);
    p = fmaf(z, p, 1.0f);
    p = z * p;
    return z > 0.f ? z : p;
}
__device__ __forceinline__ void mma16816(float* c, uint32_t a0, uint32_t a1,
                                         uint32_t a2, uint32_t a3,
                                         uint32_t b0, uint32_t b1) {
    asm volatile(
        "mma.sync.aligned.m16n8k16.row.col.f32.f16.f16.f32 "
        "{%0,%1,%2,%3}, {%4,%5,%6,%7}, {%8,%9}, {%0,%1,%2,%3};"
        : "+f"(c[0]), "+f"(c[1]), "+f"(c[2]), "+f"(c[3])
        : "r"(a0), "r"(a1), "r"(a2), "r"(a3), "r"(b0), "r"(b1));
}
__device__ __forceinline__ void cp_async16(uint32_t saddr, const void* gptr) {
    asm volatile("cp.async.cg.shared.global [%0], [%1], 16;" :: "r"(saddr), "l"(gptr));
}
#define CP_COMMIT() asm volatile("cp.async.commit_group;" ::: "memory")
#define CP_WAIT0()  asm volatile("cp.async.wait_group 0;" ::: "memory")
#define CP_WAIT1()  asm volatile("cp.async.wait_group 1;" ::: "memory")
#define LDMX4(a0, a1, a2, a3, p)                                                 \
    asm volatile("ldmatrix.sync.aligned.m8n8.x4.shared.b16 {%0,%1,%2,%3}, [%4];" \
                 : "=r"(a0), "=r"(a1), "=r"(a2), "=r"(a3) : "r"(p))

/* gemm chunk: 5 k-tiles, 2 m-tiles per warp, B from smem stage.
   chunk = smem chunk base; per (kt,nhq) 1280-B block: 2x uint4 pairs + uint2 */
__device__ __forceinline__ void gemm_chunk(float* acc, uint32_t ap0, uint32_t ap1,
                                           int h, const char* chunk,
                                           int nhq1280, int l) {
#pragma unroll
    for (int kt = 0; kt < 5; ++kt) {
        uint32_t a0, a1, a2, a3, c0, c1, c2, c3;
        LDMX4(a0, a1, a2, a3, ap0 + (h * 5 + kt) * 32);
        LDMX4(c0, c1, c2, c3, ap1 + (h * 5 + kt) * 32);
        const char* p = chunk + kt * 5120 + nhq1280;
        uint4 q0 = *(const uint4*)(p + l * 16);
        uint4 q1 = *(const uint4*)(p + 512 + l * 16);
        uint2 q2 = *(const uint2*)(p + 1024 + l * 8);
        mma16816(acc + 0,  a0, a1, a2, a3, q0.x, q0.y);
        mma16816(acc + 4,  c0, c1, c2, c3, q0.x, q0.y);
        mma16816(acc + 8,  a0, a1, a2, a3, q0.z, q0.w);
        mma16816(acc + 12, c0, c1, c2, c3, q0.z, q0.w);
        mma16816(acc + 16, a0, a1, a2, a3, q1.x, q1.y);
        mma16816(acc + 20, c0, c1, c2, c3, q1.x, q1.y);
        mma16816(acc + 24, a0, a1, a2, a3, q1.z, q1.w);
        mma16816(acc + 28, c0, c1, c2, c3, q1.z, q1.w);
        mma16816(acc + 32, a0, a1, a2, a3, q2.x, q2.y);
        mma16816(acc + 36, c0, c1, c2, c3, q2.x, q2.y);
    }
}

/* --------------- kernel 0: merged prep (B fragments + params) + weights ---
   512 threads/block.
   blocks [0,64): selection weights; blocks [64,99): fragment conversion     */
__global__ void pre_kernel(const float* __restrict__ W2,
                           const float* __restrict__ oW1,
                           const float* __restrict__ oW2,
                           const float* __restrict__ oWg,
                           const float* __restrict__ W1,
                           const float* __restrict__ b1,
                           const float* __restrict__ b2,
                           const float* __restrict__ Wg,
                           const float* __restrict__ bg,
                           const float* __restrict__ lng,
                           const float* __restrict__ lnb,
                           const float* __restrict__ x,
                           const float* __restrict__ Ww,
                           const float* __restrict__ bw,
                           float* __restrict__ out_tail) {
    extern __shared__ float stile[];   /* 160x160 fp32 (conv blocks) */
    if (blockIdx.x >= BB) {
        int t = blockIdx.x - BB;   /* 0..34 */
        const float* src = (t < 32) ? (W2 + (size_t)t * HH * HH)
                                    : (t == 32 ? oW1 : (t == 33 ? oWg : oW2));
        {
            const float4* s4 = (const float4*)src;
            float4* d4 = (float4*)stile;
            for (int i = threadIdx.x; i < HH * HH / 4; i += blockDim.x)
                d4[i] = s4[i];
        }
        __syncthreads();
        for (int idx = threadIdx.x; idx < 6400; idx += blockDim.x) {
            int kt = idx / 640;
            int nt = (idx / 32) % 20;
            int l  = idx & 31;
            int k0 = kt * 16 + (l & 3) * 2;
            int n  = nt * 8 + (l >> 2);
            uint2 v;
            v.x = pack_h2(stile[k0 * HH + n],       stile[(k0 + 1) * HH + n]);
            v.y = pack_h2(stile[(k0 + 8) * HH + n], stile[(k0 + 9) * HH + n]);
            int nhq = nt / 5, j = nt - nhq * 5;
            int dst = kt * 640 + nhq * 160 +
                      (j < 4 ? ((j >> 1) * 64 + l * 2 + (j & 1)) : (128 + l));
            g_Bfrag[(size_t)t * 6400 + dst] = v;
        }
        if (t < FF) {
            const float* srcs[7] = { W1 + t * HH, b1 + t * HH, b2 + t * HH,
                                     Wg + t * HH, bg + t * HH,
                                     lng + t * HH, lnb + t * HH };
            for (int jl = threadIdx.x; jl < 1120; jl += blockDim.x) {
                int a = jl / 160, c = jl - a * 160;
                int p;
                if (a < 2) {
                    p = a * 160 + c;
                } else {
                    int g = c / 40, rem = c - g * 40;
                    int j = rem >> 3, tt = (rem >> 1) & 3, e = rem & 1;
                    p = 320 + (a - 2) * 192 + g * 48 + tt * 12 + j * 2 + e;
                }
                g_Par[t * 1280 + p] = srcs[a][c];
            }
        }
        return;
    }
    int b = blockIdx.x;
    int tid = threadIdx.x;
    int c = tid & 31, g = tid >> 5;   /* g in 0..15 */
    const float* xb = x + b * (TT * FF);
    float a0 = 0.f, a1 = 0.f, a2 = 0.f, a3 = 0.f;
#pragma unroll 4
    for (int i = 0; i < TT * FF; i += 64) {
        int r = g + i;
        a0 = fmaf(xb[r],      Ww[r * FF + c],        a0);
        a1 = fmaf(xb[r + 16], Ww[(r + 16) * FF + c], a1);
        a2 = fmaf(xb[r + 32], Ww[(r + 32) * FF + c], a2);
        a3 = fmaf(xb[r + 48], Ww[(r + 48) * FF + c], a3);
    }
    float acc = (a0 + a1) + (a2 + a3);
    __shared__ float red[16][32];
    red[g][c] = acc;
    __syncthreads();
    if (tid < 32) {
        float s = 0.f;
#pragma unroll
        for (int i = 0; i < 16; ++i) s += red[i][tid];
        s += bw[tid];
        float m = s;
#pragma unroll
        for (int o = 16; o; o >>= 1) m = fmaxf(m, __shfl_xor_sync(0xffffffffu, m, o));
        float e = expf(s - m);
        float se = e;
#pragma unroll
        for (int o = 16; o; o >>= 1) se += __shfl_xor_sync(0xffffffffu, se, o);
        float w = e / se;
        g_weights[b * 32 + tid] = w;
        out_tail[b * 32 + tid] = w;
    }
}

/* ------------------------- kernel 1: fused VSN (HMMA) ---------------------
   SMEM (bytes):
     xs      [0,       8448)   64 x 33 fp32
     eaA     [8448,   29952)   64 x 168 fp16
     red     [29952,  32000)   64 x 8 fp32
     pbuf    [32000,  47360)   3 x 5120 param ring
     Bstage  [47360,  98560)   2 x 25600 cp.async double buffer              */
#define OFF_EAA  8448
#define OFF_RED  29952
#define OFF_PBUF 32000
#define OFF_BST  47360
#define CHKB     25600
#define SMEM_TOTAL 98560

__global__ void __launch_bounds__(NTH, 2)
fused_mma(const float* __restrict__ x,
          const float* __restrict__ ob1, const float* __restrict__ ob2,
          const float* __restrict__ obg,
          const float* __restrict__ olng, const float* __restrict__ olnb,
          float* __restrict__ out) {
    extern __shared__ char smem[];
    float*  xs  = (float*)smem;
    __half* eaA = (__half*)(smem + OFF_EAA);
    float*  red = (float*)(smem + OFF_RED);
    const uint32_t sbase = smem_u32(smem);

    const int tid = threadIdx.x;
    const int l = tid & 31, wid = tid >> 5;
    const int mg = wid >> 2, nhq = wid & 3;
    const int rA = mg * 32 + (l >> 2);
    int rr[4];
    rr[0] = rA; rr[1] = rA + 8; rr[2] = rA + 16; rr[3] = rA + 24;
    const int colbq = nhq * 40;
    const int colt = (l & 3) * 2;
    const int pbase12 = nhq * 48 + (l & 3) * 12;
    const int nhq1280 = nhq * 1280;
    const int m0 = blockIdx.x * TM;
    const int bb = blockIdx.x >> 2;

    const int lrow = mg * 32 + (l & 15);
    const int lcol = (l >> 4) * 8;
    const uint32_t aAp0 = sbase + OFF_EAA + (lrow * EAS + lcol) * 2;
    const uint32_t aAp1 = aAp0 + 16 * EAS * 2;

    const int grow = tid >> 2;
    const int gcb = (tid & 3) * 40;

    const u64 SC1  = packf2(2.0833333e-3f, 2.0833333e-3f);
    const u64 SC2  = packf2(-2.0833334e-2f, -2.0833334e-2f);
    const u64 SC3  = packf2(0.25f, 0.25f);
    const u64 SCH  = packf2(0.5f, 0.5f);
    const u64 C120 = packf2(8.3333333e-3f, 8.3333333e-3f);
    const u64 C24  = packf2(4.1666667e-2f, 4.1666667e-2f);
    const u64 C6   = packf2(1.6666667e-1f, 1.6666667e-1f);

    const char* buf0 = smem + OFF_BST;
    const char* buf1 = smem + OFF_BST + CHKB;

#define HBAR() asm volatile("bar.sync %0, 128;" :: "r"(1 + mg) : "memory")

#define PREF_CHUNK(cc, bufi) do {                                                \
    const uint4* gsrc = (const uint4*)g_Bfrag + (size_t)(cc) * 1600;             \
    const uint32_t dst = sbase + OFF_BST + (bufi) * CHKB;                        \
    for (int j = tid; j < 1600; j += NTH)                                        \
        cp_async16(dst + j * 16, gsrc + j);                                      \
} while (0)

#define PREF_PAR(ff) do {                                                        \
    const float4* psrc = (const float4*)g_Par + (size_t)(ff) * 320;              \
    const uint32_t pdst = sbase + OFF_PBUF + ((ff) % 3) * 5120;                  \
    for (int j = tid; j < 320; j += NTH)                                         \
        cp_async16(pdst + j * 16, psrc + j);                                     \
} while (0)

#define AGEN(ff, slot) do {                                                      \
    const float* pbn = (const float*)(smem + OFF_PBUF) + (slot) * 1280;          \
    const float xvg = xs[grow * XSTR + (ff)];                                    \
    const u64 xg2 = packf2(xvg, xvg);                                            \
    const u64* W1u = (const u64*)(pbn + gcb);                                    \
    const u64* b1u = (const u64*)(pbn + 160 + gcb);                              \
    uint4* eg = (uint4*)(eaA + grow * EAS + gcb);                                \
    _Pragma("unroll")                                                            \
    for (int q = 0; q < 5; ++q) {                                                \
        uint4 o;                                                                 \
        o.x = agen2(xg2, W1u[4 * q + 0], b1u[4 * q + 0], C120, C24, C6, SCH);    \
        o.y = agen2(xg2, W1u[4 * q + 1], b1u[4 * q + 1], C120, C24, C6, SCH);    \
        o.z = agen2(xg2, W1u[4 * q + 2], b1u[4 * q + 2], C120, C24, C6, SCH);    \
        o.w = agen2(xg2, W1u[4 * q + 3], b1u[4 * q + 3], C120, C24, C6, SCH);    \
        eg[q] = o;                                                               \
    }                                                                            \
} while (0)

#define EPILOGUE(fe, slotE) do {                                                 \
    const float* pe = (const float*)(smem + OFF_PBUF) + (slotE) * 1280;          \
    float wbf = g_weights[bb * FF + (fe)];                                       \
    u64 xv2[4], nxv2[4], nc02[4], s1p[4], s2p[4];                                \
    float c0v[4];                                                                \
    _Pragma("unroll")                                                            \
    for (int ri = 0; ri < 4; ++ri) {                                             \
        float xv = xs[rr[ri] * XSTR + (fe)];                                     \
        float c0 = 0.5f * xv;                                                    \
        xv2[ri]  = packf2(xv, xv);                                               \
        nxv2[ri] = packf2(-xv, -xv);                                             \
        nc02[ri] = packf2(-c0, -c0);                                             \
        c0v[ri]  = c0;                                                           \
        s1p[ri] = 0ull; s2p[ri] = 0ull;                                          \
    }                                                                            \
    u64 featp[20];                                                               \
    {                                                                            \
        const u64* pB2 = (const u64*)(pe + 320 + pbase12);                       \
        const u64* pWg = (const u64*)(pe + 512 + pbase12);                       \
        const u64* pBg = (const u64*)(pe + 704 + pbase12);                       \
        _Pragma("unroll")                                                        \
        for (int jv = 0; jv < 5; ++jv) {                                         \
            u64 b2p = pB2[jv], wgp = pWg[jv], bgp = pBg[jv];                     \
            _Pragma("unroll")                                                    \
            for (int ri = 0; ri < 4; ++ri) {                                     \
                int idx = (jv * 2 + (ri >> 1)) * 4 + (ri & 1) * 2;               \
                u64 ap = packf2(acc[idx], acc[idx + 1]);                         \
                u64 a2; ADD2(a2, ap, b2p);                                       \
                u64 gz; FMA2(gz, xv2[ri], wgp, bgp);                             \
                u64 gv = fsig2(gz, SC1, SC2, SC3, SCH);                          \
                u64 dmx; ADD2(dmx, a2, nxv2[ri]);                                \
                u64 ft; FMA2(ft, gv, dmx, xv2[ri]);                              \
                featp[jv * 4 + ri] = ft;                                         \
                u64 d; ADD2(d, ft, nc02[ri]);                                    \
                ADD2(s1p[ri], s1p[ri], d);                                       \
                FMA2(s2p[ri], d, d, s2p[ri]);                                    \
            }                                                                    \
        }                                                                        \
    }                                                                            \
    float s1v[4], s2v[4];                                                        \
    _Pragma("unroll")                                                            \
    for (int ri = 0; ri < 4; ++ri) {                                             \
        float a_, b_;                                                            \
        unpackf2(a_, b_, s1p[ri]); s1v[ri] = a_ + b_;                            \
        unpackf2(a_, b_, s2p[ri]); s2v[ri] = a_ + b_;                            \
    }                                                                            \
    _Pragma("unroll")                                                            \
    for (int ri = 0; ri < 4; ++ri) {                                             \
        _Pragma("unroll")                                                        \
        for (int o = 1; o < 4; o <<= 1) {                                        \
            s1v[ri] += __shfl_xor_sync(0xffffffffu, s1v[ri], o);                 \
            s2v[ri] += __shfl_xor_sync(0xffffffffu, s2v[ri], o);                 \
        }                                                                        \
    }                                                                            \
    if ((l & 3) == 0) {                                                          \
        _Pragma("unroll")                                                        \
        for (int ri = 0; ri < 4; ++ri)                                           \
            *(float2*)(red + rr[ri] * 8 + nhq * 2) = make_float2(s1v[ri], s2v[ri]); \
    }                                                                            \
    HBAR();                                                                      \
    u64 inv2[4], nmi2[4];                                                        \
    _Pragma("unroll")                                                            \
    for (int ri = 0; ri < 4; ++ri) {                                             \
        float4 qa = *(const float4*)(red + rr[ri] * 8);                          \
        float4 qb = *(const float4*)(red + rr[ri] * 8 + 4);                      \
        float S1 = (qa.x + qa.z) + (qb.x + qb.z);                                \
        float S2 = (qa.y + qa.w) + (qb.y + qb.w);                                \
        float dm = S1 * (1.f / 160.f);                                           \
        float var = fmaf(-dm, dm, S2 * (1.f / 160.f));                           \
        float inv = rsqrtf(var + 1e-3f);                                         \
        float nmi = -(c0v[ri] + dm) * inv;                                       \
        inv2[ri] = packf2(inv, inv);                                             \
        nmi2[ri] = packf2(nmi, nmi);                                             \
    }                                                                            \
    {                                                                            \
        u64 wbf2 = packf2(wbf, wbf);                                             \
        const u64* pLg = (const u64*)(pe + 896 + pbase12);                       \
        const u64* pLb = (const u64*)(pe + 1088 + pbase12);                      \
        _Pragma("unroll")                                                        \
        for (int jv = 0; jv < 5; ++jv) {                                         \
            u64 lgp = pLg[jv], lbp = pLb[jv];                                    \
            _Pragma("unroll")                                                    \
            for (int ri = 0; ri < 4; ++ri) {                                     \
                u64 yt; FMA2(yt, featp[jv * 4 + ri], inv2[ri], nmi2[ri]);        \
                u64 y;  FMA2(y, yt, lgp, lbp);                                   \
                FMA2(comb2[jv * 4 + ri], wbf2, y, comb2[jv * 4 + ri]);           \
            }                                                                    \
        }                                                                        \
    }                                                                            \
} while (0)

    /* ------------------------------ preamble ------------------------------ */
    {
        const float4* xsrc = (const float4*)(x + (size_t)m0 * FF);
        for (int i = tid; i < TM * FF / 4; i += NTH) {
            float4 v = xsrc[i];
            float* d = xs + (i >> 3) * XSTR + ((i & 7) << 2);
            d[0] = v.x; d[1] = v.y; d[2] = v.z; d[3] = v.w;
        }
    }
    PREF_PAR(0);
    CP_COMMIT();
    u64 comb2[20];
#pragma unroll
    for (int i = 0; i < 20; ++i) comb2[i] = 0ull;
    CP_WAIT0();
    __syncthreads();

    float acc[40];

    /* ========================= phase 1: f loop ============================ */
    for (int f = 0; f < FF; ++f) {
        const int sc = f % 3;
        __syncthreads();
        PREF_CHUNK(2 * f, 0);
        if (f + 1 < FF) PREF_PAR(f + 1);
        CP_COMMIT();
        PREF_CHUNK(2 * f + 1, 1);
        CP_COMMIT();

        AGEN(f, sc);
        if (f > 0) EPILOGUE(f - 1, (f - 1) % 3);

#pragma unroll
        for (int i = 0; i < 40; ++i) acc[i] = 0.f;
        CP_WAIT1();
        __syncthreads();
        gemm_chunk(acc, aAp0, aAp1, 0, buf0, nhq1280, l);
        CP_WAIT0();
        __syncthreads();
        gemm_chunk(acc, aAp0, aAp1, 1, buf1, nhq1280, l);
    }

    /* ========================= phase 2: output MLP ======================== */
    __syncthreads();
    PREF_CHUNK(64, 0); CP_COMMIT();
    PREF_CHUNK(65, 1); CP_COMMIT();
    EPILOGUE(31, 31 % 3);
#pragma unroll
    for (int jv = 0; jv < 5; ++jv)
#pragma unroll
        for (int ri = 0; ri < 4; ++ri) {
            float cx, cy;
            unpackf2(cx, cy, comb2[jv * 4 + ri]);
            *(uint32_t*)(eaA + rr[ri] * EAS + colbq + jv * 8 + colt) = pack_h2(cx, cy);
        }

    /* G1: h1 = elu(comb @ oW1 + ob1) */
#pragma unroll
    for (int i = 0; i < 40; ++i) acc[i] = 0.f;
    CP_WAIT1(); __syncthreads(); gemm_chunk(acc, aAp0, aAp1, 0, buf0, nhq1280, l);
    CP_WAIT0(); __syncthreads(); gemm_chunk(acc, aAp0, aAp1, 1, buf1, nhq1280, l);
    uint32_t h1p[20];
#pragma unroll
    for (int jv = 0; jv < 5; ++jv)
#pragma unroll
        for (int ri = 0; ri < 4; ++ri) {
            int idx = (jv * 2 + (ri >> 1)) * 4 + (ri & 1) * 2;
            int col = colbq + jv * 8 + colt;
            float2 vb = *(const float2*)(ob1 + col);
            h1p[jv * 4 + ri] =
                pack_h2(felu(acc[idx] + vb.x), felu(acc[idx + 1] + vb.y));
        }

    /* G3: og = sigmoid(comb @ oWg + obg) */
    __syncthreads();
    PREF_CHUNK(66, 0); CP_COMMIT();
    PREF_CHUNK(67, 1); CP_COMMIT();
#pragma unroll
    for (int i = 0; i < 40; ++i) acc[i] = 0.f;
    CP_WAIT1(); __syncthreads(); gemm_chunk(acc, aAp0, aAp1, 0, buf0, nhq1280, l);
    CP_WAIT0(); __syncthreads(); gemm_chunk(acc, aAp0, aAp1, 1, buf1, nhq1280, l);
    u64 og2[20];
#pragma unroll
    for (int jv = 0; jv < 5; ++jv)
#pragma unroll
        for (int ri = 0; ri < 4; ++ri) {
            int idx = (jv * 2 + (ri >> 1)) * 4 + (ri & 1) * 2;
            int col = colbq + jv * 8 + colt;
            float2 vb = *(const float2*)(obg + col);
            og2[jv * 4 + ri] = packf2(fsigmoid(acc[idx] + vb.x),
                                      fsigmoid(acc[idx + 1] + vb.y));
        }

    /* G2: oa = h1 @ oW2 + ob2 */
    __syncthreads();
    PREF_CHUNK(68, 0); CP_COMMIT();
    PREF_CHUNK(69, 1); CP_COMMIT();
#pragma unroll
    for (int jv = 0; jv < 5; ++jv)
#pragma unroll
        for (int ri = 0; ri < 4; ++ri)
            *(uint32_t*)(eaA + rr[ri] * EAS + colbq + jv * 8 + colt) = h1p[jv * 4 + ri];
#pragma unroll
    for (int i = 0; i < 40; ++i) acc[i] = 0.f;
    CP_WAIT1(); __syncthreads(); gemm_chunk(acc, aAp0, aAp1, 0, buf0, nhq1280, l);
    CP_WAIT0(); __syncthreads(); gemm_chunk(acc, aAp0, aAp1, 1, buf1, nhq1280, l);

    /* combine + final LN + fragment-layout store */
    {
        u64 vp[20];
        float s1v[4] = {0.f, 0.f, 0.f, 0.f};
        float s2v[4] = {0.f, 0.f, 0.f, 0.f};
#pragma unroll
        for (int jv = 0; jv < 5; ++jv)
#pragma unroll
            for (int ri = 0; ri < 4; ++ri) {
                int idx = (jv * 2 + (ri >> 1)) * 4 + (ri & 1) * 2;
                int col = colbq + jv * 8 + colt;
                float2 vb = *(const float2*)(ob2 + col);
                float oax = acc[idx] + vb.x;
                float oay = acc[idx + 1] + vb.y;
                float ogx, ogy, cx, cy;
                unpackf2(ogx, ogy, og2[jv * 4 + ri]);
                unpackf2(cx, cy, comb2[jv * 4 + ri]);
                float vx = fmaf(ogx, oax - cx, cx);
                float vy = fmaf(ogy, oay - cy, cy);
                vp[jv * 4 + ri] = packf2(vx, vy);
                s1v[ri] += vx + vy;
                s2v[ri] = fmaf(vx, vx, s2v[ri]);
                s2v[ri] = fmaf(vy, vy, s2v[ri]);
            }
#pragma unroll
        for (int ri = 0; ri < 4; ++ri) {
#pragma unroll
            for (int o = 1; o < 4; o <<= 1) {
                s1v[ri] += __shfl_xor_sync(0xffffffffu, s1v[ri], o);
                s2v[ri] += __shfl_xor_sync(0xffffffffu, s2v[ri], o);
            }
        }
        if ((l & 3) == 0) {
#pragma unroll
            for (int ri = 0; ri < 4; ++ri)
                *(float2*)(red + rr[ri] * 8 + nhq * 2) = make_float2(s1v[ri], s2v[ri]);
        }
        HBAR();
        float meanv[4], invv[4];
#pragma unroll
        for (int ri = 0; ri < 4; ++ri) {
            float4 qa = *(const float4*)(red + rr[ri] * 8);
            float4 qb = *(const float4*)(red + rr[ri] * 8 + 4);
            float S1 = (qa.x + qa.z) + (qb.x + qb.z);
            float S2 = (qa.y + qa.w) + (qb.y + qb.w);
            float mean = S1 * (1.f / 160.f);
            float var = fmaf(-mean, mean, S2 * (1.f / 160.f));
            meanv[ri] = mean;
            invv[ri] = rsqrtf(var + 1e-3f);
        }
#pragma unroll
        for (int jv = 0; jv < 5; ++jv)
#pragma unroll
            for (int ri = 0; ri < 4; ++ri) {
                int col = colbq + jv * 8 + colt;
                float2 lg = *(const float2*)(olng + col);
                float2 lb = *(const float2*)(olnb + col);
                float vx, vy;
                unpackf2(vx, vy, vp[jv * 4 + ri]);
                float2 o;
                o.x = fmaf((vx - meanv[ri]) * invv[ri], lg.x, lb.x);
                o.y = fmaf((vy - meanv[ri]) * invv[ri], lg.y, lb.y);
                *(float2*)(out + (size_t)(m0 + rr[ri]) * HH + col) = o;
            }
    }
#undef HBAR
#undef AGEN
#undef EPILOGUE
#undef PREF_CHUNK
#undef PREF_PAR
}

/* --------------------------------- launch --------------------------------- */
extern "C" void kernel_launch(void* const* d_in, const int* in_sizes, int n_in,
                              void* d_out, int out_size) {
    const float* x    = (const float*)d_in[0];
    const float* W1   = (const float*)d_in[1];
    const float* b1   = (const float*)d_in[2];
    const float* W2   = (const float*)d_in[3];
    const float* b2   = (const float*)d_in[4];
    const float* Wg   = (const float*)d_in[5];
    const float* bg   = (const float*)d_in[6];
    const float* lng  = (const float*)d_in[7];
    const float* lnb  = (const float*)d_in[8];
    const float* Ww   = (const float*)d_in[9];
    const float* bw   = (const float*)d_in[10];
    const float* oW1  = (const float*)d_in[11];
    const float* ob1  = (const float*)d_in[12];
    const float* oW2  = (const float*)d_in[13];
    const float* ob2  = (const float*)d_in[14];
    const float* oWg  = (const float*)d_in[15];
    const float* obg  = (const float*)d_in[16];
    const float* olng = (const float*)d_in[17];
    const float* olnb = (const float*)d_in[18];
    float* out = (float*)d_out;

    const int pre_smem = HH * HH * (int)sizeof(float);   /* 102400 */
    cudaFuncSetAttribute(pre_kernel, cudaFuncAttributeMaxDynamicSharedMemorySize,
                         pre_smem);
    cudaFuncSetAttribute(fused_mma, cudaFuncAttributeMaxDynamicSharedMemorySize,
                         SMEM_TOTAL);

    pre_kernel<<<BB + 35, 512, pre_smem>>>(W2, oW1, oW2, oWg,
                                           W1, b1, b2, Wg, bg, lng, lnb,
                                           x, Ww, bw, out + (size_t)BB * TT * HH);
    fused_mma<<<(BB * TT) / TM, NTH, SMEM_TOTAL>>>(
        x, ob1, ob2, obg, olng, olnb, out);
}